// round 9
// baseline (speedup 1.0000x reference)
#include <cuda_runtime.h>
#include <cuda_bf16.h>
#include <math.h>

typedef unsigned long long ull;

#define SCALE 0.08838834764831843f

// ----------------------------- device scratch -------------------------------
__device__ float  g_qkvp[8 * 32 * 6144];          // k-split partials (QKV)
__device__ float  g_qkv [32 * 6144];              // reduced qkv + bias
__device__ float  g_rqdup[3 * 2 * 32 * 16 * 256]; // roped q, 3 pos-sets, DUPLICATED pairs
__device__ float  g_knew[2 * 8 * 16 * 128];       // roped new keys
__device__ float  g_vnew[2 * 8 * 16 * 128];       // new values
__device__ float  g_pm [16 * 98 * 64];            // split-K partial max
__device__ float  g_pl [16 * 98 * 64];            // split-K partial sum
__device__ float  g_pacc[16 * 98 * 64 * 128];     // split-K partial accum (unnormalized)
__device__ float  g_attn[32 * 4096];              // attention output tokens x (H*D)
__device__ float  g_op [8 * 32 * 4096];           // k-split partials (O proj)
__device__ float2 g_qcs[3 * 2 * 16 * 64];         // q-rope cos/sin table

// ----------------------------- f32x2 helpers --------------------------------
__device__ __forceinline__ ull ffma2(ull a, ull b, ull c) {
    ull d;
    asm("fma.rn.f32x2 %0, %1, %2, %3;" : "=l"(d) : "l"(a), "l"(b), "l"(c));
    return d;
}
__device__ __forceinline__ ull pk2(float x, float y) {
    ull r;
    asm("mov.b64 %0, {%1, %2};" : "=l"(r) : "f"(x), "f"(y));
    return r;
}
__device__ __forceinline__ float2 unpk(ull v) {
    float2 r;
    asm("mov.b64 {%0, %1}, %2;" : "=f"(r.x), "=f"(r.y) : "l"(v));
    return r;
}

// ----------------------------- rope tables ----------------------------------
// loc bases: seg0: 12304 (both workers); seg1: w0->2048, w1->4112; seg2: w0->4112, w1->2048
__global__ void qcs_kernel() {
    int j  = threadIdx.x;          // 0..63
    int b  = blockIdx.x;           // 0..95
    int qi = b & 15;
    int w  = (b >> 4) & 1;
    int seg = b >> 5;
    int base = (seg == 0) ? 12304 : (seg == 1) ? ((w == 0) ? 2048 : 4112)
                                               : ((w == 0) ? 4112 : 2048);
    // inv = theta^(-j/64), computed in double then rounded like the f32 reference path
    double inv = exp(-(double)j * 0.14391156831212787);   // ln(10000)/64
    float invf = (float)inv;
    float angf = (float)(base + qi) * invf;               // f32 rounding like reference
    double ang = (double)angf;
    g_qcs[((seg * 2 + w) * 16 + qi) * 64 + j] =
        make_float2((float)cos(ang), (float)sin(ang));
}

// q rope: grid 3*2*32*16 blocks x 128 threads; writes DUPLICATED pairs
__global__ void rope_q_kernel() {
    int d  = threadIdx.x;
    int b  = blockIdx.x;
    int qi = b & 15;
    int h  = (b >> 4) & 31;
    int w  = (b >> 9) & 1;
    int seg = b >> 10;
    int t = w * 16 + qi;
    float qv  = g_qkv[t * 6144 + h * 128 + d];
    float rot = (d < 64) ? -g_qkv[t * 6144 + h * 128 + d + 64]
                         :  g_qkv[t * 6144 + h * 128 + d - 64];
    float2 cs = g_qcs[((seg * 2 + w) * 16 + qi) * 64 + (d & 63)];
    float r = qv * cs.x + rot * cs.y;
    size_t o = ((size_t)(((seg * 2 + w) * 32 + h) * 16 + qi)) * 256 + 2 * d;
    g_rqdup[o] = r;
    g_rqdup[o + 1] = r;
}

// k/v new: grid 2*8*16 x 128
__global__ void rope_kv_kernel(const float* __restrict__ cosn,
                               const float* __restrict__ sinn) {
    int d  = threadIdx.x;
    int b  = blockIdx.x;
    int qi = b & 15;
    int kv = (b >> 4) & 7;
    int w  = b >> 7;
    int t = w * 16 + qi;
    float c = cosn[(w * 16 + qi) * 128 + d];
    float s = sinn[(w * 16 + qi) * 128 + d];
    float k   = g_qkv[t * 6144 + 4096 + kv * 128 + d];
    float rot = (d < 64) ? -g_qkv[t * 6144 + 4096 + kv * 128 + d + 64]
                         :  g_qkv[t * 6144 + 4096 + kv * 128 + d - 64];
    int o = ((w * 8 + kv) * 16 + qi) * 128 + d;
    g_knew[o] = k * c + rot * s;
    g_vnew[o] = g_qkv[t * 6144 + 5120 + kv * 128 + d];
}

// ----------------------------- generic GEMM ---------------------------------
// C[t][o] = sum_k A[t][k]*W[o][k]; A is 32 x K (row stride K); k-split partials.
// dst: 0 -> g_qkvp, 1 -> g_op.   asel: 1 -> A = g_attn.
__global__ __launch_bounds__(256) void gemm_kernel(
    const float* __restrict__ Ap, const float* __restrict__ W,
    int dst, int asel, int ldC, int colOff, int K, int KC) {
    __shared__ float As[64][34];    // [k][t], even stride for 8B loads
    __shared__ float Ws[64][132];   // [k][o], 16B-aligned rows
    const float* A = asel ? g_attn : Ap;
    float* Cp = dst ? g_op : g_qkvp;

    int tid = threadIdx.x;
    int o0  = blockIdx.x * 128;
    int kb  = blockIdx.y * KC;
    int to  = tid & 31;     // 4 o per thread
    int tt  = tid >> 5;     // 4 t per thread

    ull c2[4][2];
#pragma unroll
    for (int i = 0; i < 4; i++)
#pragma unroll
        for (int p = 0; p < 2; p++) c2[i][p] = 0ULL;

    for (int kk = 0; kk < KC; kk += 64) {
#pragma unroll
        for (int r = 0; r < 2; r++) {            // A tile 32t x 64k
            int f = tid + r * 256;
            int t = f & 31, kq = f >> 5;
            float4 av = *(const float4*)&A[(size_t)t * K + kb + kk + 4 * kq];
            As[4 * kq + 0][t] = av.x;
            As[4 * kq + 1][t] = av.y;
            As[4 * kq + 2][t] = av.z;
            As[4 * kq + 3][t] = av.w;
        }
#pragma unroll
        for (int r = 0; r < 8; r++) {            // W tile 128o x 64k
            int f = tid + r * 256;
            int o = f & 127, kq = f >> 7;
            float4 wv = *(const float4*)&W[(size_t)(o0 + o) * K + kb + kk + 4 * kq];
            Ws[4 * kq + 0][o] = wv.x;
            Ws[4 * kq + 1][o] = wv.y;
            Ws[4 * kq + 2][o] = wv.z;
            Ws[4 * kq + 3][o] = wv.w;
        }
        __syncthreads();
#pragma unroll 8
        for (int k = 0; k < 64; k++) {
            ull a0 = *(const ull*)&As[k][4 * tt];       // t-pair (4tt,4tt+1)
            ull a1 = *(const ull*)&As[k][4 * tt + 2];   // (4tt+2,4tt+3)
            float4 wv = *(const float4*)&Ws[k][4 * to];
            ull w0 = pk2(wv.x, wv.x), w1 = pk2(wv.y, wv.y);
            ull w2 = pk2(wv.z, wv.z), w3 = pk2(wv.w, wv.w);
            c2[0][0] = ffma2(w0, a0, c2[0][0]); c2[0][1] = ffma2(w0, a1, c2[0][1]);
            c2[1][0] = ffma2(w1, a0, c2[1][0]); c2[1][1] = ffma2(w1, a1, c2[1][1]);
            c2[2][0] = ffma2(w2, a0, c2[2][0]); c2[2][1] = ffma2(w2, a1, c2[2][1]);
            c2[3][0] = ffma2(w3, a0, c2[3][0]); c2[3][1] = ffma2(w3, a1, c2[3][1]);
        }
        __syncthreads();
    }
    int ks = blockIdx.y;
#pragma unroll
    for (int i = 0; i < 4; i++) {
        int o = o0 + 4 * to + i;
#pragma unroll
        for (int p = 0; p < 2; p++) {
            float2 v = unpk(c2[i][p]);
            int t0 = 4 * tt + 2 * p;
            Cp[(size_t)(ks * 32 + t0) * ldC + colOff + o]     = v.x;
            Cp[(size_t)(ks * 32 + t0 + 1) * ldC + colOff + o] = v.y;
        }
    }
}

__global__ void reduce_qkv_kernel(const float* __restrict__ bq,
                                  const float* __restrict__ bk,
                                  const float* __restrict__ bv) {
    int idx = blockIdx.x * 256 + threadIdx.x;   // < 196608
    float s = 0.f;
#pragma unroll
    for (int ks = 0; ks < 8; ks++) s += g_qkvp[(size_t)ks * 196608 + idx];
    int o = idx % 6144;
    float b = (o < 4096) ? bq[o] : (o < 5120 ? bk[o - 4096] : bv[o - 5120]);
    g_qkv[idx] = s + b;
}

__global__ void reduce_out_kernel(float* __restrict__ out) {
    int idx = blockIdx.x * 256 + threadIdx.x;   // < 131072
    float s = 0.f;
#pragma unroll
    for (int ks = 0; ks < 8; ks++) s += g_op[(size_t)ks * 131072 + idx];
    out[idx] = s;
}

// ----------------------------- attention ------------------------------------
// grid (98 chunks, 16 = w*8+kv), 256 threads, ~194KB dynamic smem.
// chunks: 0..63 shared seg (128 keys each); 64..79 w0 cache; 80 seg1 new (16);
//         81..96 w1 cache; 97 seg2 new (16).
__global__ __launch_bounds__(256) void attn_kernel(
    const float* __restrict__ ssk, const float* __restrict__ ssv,
    const float* __restrict__ w0k, const float* __restrict__ w0v,
    const float* __restrict__ w1k, const float* __restrict__ w1v) {
    extern __shared__ float sm[];
    float* KV = sm;                 // 16896 floats: Kt[d][l] stride 132, later V[l][d]
    float* SC = sm + 16896;         // 16384: duplicated scores/probs [hh][q][256]
    float* RQ = sm + 33280;         // 16384: duplicated roped q      [hh][q][256]
    __shared__ float redm[64][4], redl[64][4], mfin[64];

    int tid = threadIdx.x;
    int cid = blockIdx.x, wkv = blockIdx.y;
    int w = wkv >> 3, kv = wkv & 7;

    int seg, nl = 128, ownnew = 0;
    const float *ksrc, *vsrc;
    if (cid < 64) {
        seg = 0;
        size_t off = ((size_t)kv * 8192 + cid * 128) * 128;
        ksrc = ssk + off; vsrc = ssv + off;
    } else if (cid < 81) {
        seg = 1;
        int cc = cid - 64;
        if (cc < 16) {
            size_t off = ((size_t)kv * 2048 + cc * 128) * 128;
            ksrc = w0k + off; vsrc = w0v + off;
        } else {
            nl = 16; ownnew = (w == 0);
            size_t off = (size_t)(0 * 8 + kv) * 16 * 128;
            ksrc = g_knew + off; vsrc = g_vnew + off;
        }
    } else {
        seg = 2;
        int cc = cid - 81;
        if (cc < 16) {
            size_t off = ((size_t)kv * 2048 + cc * 128) * 128;
            ksrc = w1k + off; vsrc = w1v + off;
        } else {
            nl = 16; ownnew = (w == 1);
            size_t off = (size_t)(1 * 8 + kv) * 16 * 128;
            ksrc = g_knew + off; vsrc = g_vnew + off;
        }
    }
    int pidx = wkv * 98 + cid;

    // load duplicated roped q for the 4 heads of this kv, this seg/worker
    {
        const float4* s4 = (const float4*)(g_rqdup +
            (size_t)((seg * 2 + w) * 32 + kv * 4) * 16 * 256);
        float4* d4 = (float4*)RQ;
        for (int i = tid; i < 4096; i += 256) d4[i] = s4[i];
    }
    // load K transposed: Kt[d][l], stride 132 (conflict-free stores: lanes vary l)
#pragma unroll
    for (int r = 0; r < 16; r++) {
        int f = tid + r * 256;
        int l = f & 127, dq = f >> 7;
        float4 v = (l < nl) ? ((const float4*)ksrc)[l * 32 + dq]
                            : make_float4(0.f, 0.f, 0.f, 0.f);
        KV[(4 * dq + 0) * 132 + l] = v.x;
        KV[(4 * dq + 1) * 132 + l] = v.y;
        KV[(4 * dq + 2) * 132 + l] = v.z;
        KV[(4 * dq + 3) * 132 + l] = v.w;
    }
    __syncthreads();

    int wi = tid >> 5, lane = tid & 31;
    int hh = wi & 3, half = wi >> 2;

    // ---- QK: warp (head hh, key-half); lane owns key pair lp,lp+1 ----
    {
        int lp = half * 64 + 2 * lane;
        ull acc[16];
#pragma unroll
        for (int q = 0; q < 16; q++) acc[q] = 0ULL;
        const float* rqh = RQ + hh * 16 * 256;
        for (int d = 0; d < 128; d += 4) {
            ull k0 = *(const ull*)&KV[(d + 0) * 132 + lp];
            ull k1 = *(const ull*)&KV[(d + 1) * 132 + lp];
            ull k2 = *(const ull*)&KV[(d + 2) * 132 + lp];
            ull k3 = *(const ull*)&KV[(d + 3) * 132 + lp];
#pragma unroll
            for (int q = 0; q < 16; q++) {
                const ulonglong2* rp = (const ulonglong2*)(rqh + q * 256 + 2 * d);
                ulonglong2 ra = rp[0], rb = rp[1];
                acc[q] = ffma2(ra.x, k0, acc[q]);
                acc[q] = ffma2(ra.y, k1, acc[q]);
                acc[q] = ffma2(rb.x, k2, acc[q]);
                acc[q] = ffma2(rb.y, k3, acc[q]);
            }
        }
#pragma unroll
        for (int q = 0; q < 16; q++) {
            float2 sc = unpk(acc[q]);
            bool ok0 = (lp < nl)     && (!ownnew || lp     <= q);
            bool ok1 = (lp + 1 < nl) && (!ownnew || lp + 1 <= q);
            float s0 = ok0 ? sc.x * SCALE : -1e30f;
            float s1 = ok1 ? sc.y * SCALE : -1e30f;
            *(float4*)&SC[(hh * 16 + q) * 256 + 2 * lp] = make_float4(s0, s0, s1, s1);
        }
    }
    __syncthreads();

    // ---- per-chunk softmax (unnormalized probs, track m and sum) ----
    {
        int hq = tid & 63, part = tid >> 6;
        float* row = SC + hq * 256;
        float m = -1e30f;
        for (int i = 0; i < 32; i++) m = fmaxf(m, row[2 * (part * 32 + i)]);
        redm[hq][part] = m;
        __syncthreads();
        if (tid < 64)
            mfin[tid] = fmaxf(fmaxf(redm[tid][0], redm[tid][1]),
                              fmaxf(redm[tid][2], redm[tid][3]));
        __syncthreads();
        float mm = mfin[hq];
        float s = 0.f;
        for (int i = 0; i < 32; i++) {
            int idx = 2 * (part * 32 + i);
            float p = __expf(row[idx] - mm);
            row[idx] = p; row[idx + 1] = p;
            s += p;
        }
        redl[hq][part] = s;
        __syncthreads();
        if (tid < 64) {
            float L = redl[tid][0] + redl[tid][1] + redl[tid][2] + redl[tid][3];
            g_pm[(size_t)pidx * 64 + tid] = mfin[tid];
            g_pl[(size_t)pidx * 64 + tid] = L;
        }
    }
    __syncthreads();

    // ---- load V (reuse KV buffer, row-major [l][128]) ----
    for (int f = tid; f < 4096; f += 256) {
        int l = f >> 5;
        float4 v = (l < nl) ? ((const float4*)vsrc)[f]
                            : make_float4(0.f, 0.f, 0.f, 0.f);
        ((float4*)KV)[f] = v;
    }
    __syncthreads();

    // ---- PV: warp (head hh, d-half); lane owns dim pair dp,dp+1 ----
    {
        int dp = half * 64 + 2 * lane;
        ull acc[16];
#pragma unroll
        for (int q = 0; q < 16; q++) acc[q] = 0ULL;
        const float* sch = SC + hh * 16 * 256;
        for (int l = 0; l < 128; l += 4) {
            ull v0 = *(const ull*)&KV[(l + 0) * 128 + dp];
            ull v1 = *(const ull*)&KV[(l + 1) * 128 + dp];
            ull v2 = *(const ull*)&KV[(l + 2) * 128 + dp];
            ull v3 = *(const ull*)&KV[(l + 3) * 128 + dp];
#pragma unroll
            for (int q = 0; q < 16; q++) {
                const ulonglong2* pp = (const ulonglong2*)(sch + q * 256 + 2 * l);
                ulonglong2 pa = pp[0], pb = pp[1];
                acc[q] = ffma2(pa.x, v0, acc[q]);
                acc[q] = ffma2(pa.y, v1, acc[q]);
                acc[q] = ffma2(pb.x, v2, acc[q]);
                acc[q] = ffma2(pb.y, v3, acc[q]);
            }
        }
#pragma unroll
        for (int q = 0; q < 16; q++) {
            float2 a = unpk(acc[q]);
            *(float2*)&g_pacc[((size_t)pidx * 64 + hh * 16 + q) * 128 + dp] = a;
        }
    }
}

// split-K combine: grid 1024 = (w,h,q), 128 threads = d
__global__ __launch_bounds__(128) void combine_kernel() {
    int d = threadIdx.x;
    int b = blockIdx.x;
    int q = b & 15, h = (b >> 4) & 31, w = b >> 9;
    int kv = h >> 2;
    int hq = (h & 3) * 16 + q;
    size_t base = (size_t)(w * 8 + kv) * 98;
    float M = -1e30f;
    for (int c = 0; c < 98; c++) M = fmaxf(M, g_pm[(base + c) * 64 + hq]);
    float L = 0.f, A = 0.f;
    for (int c = 0; c < 98; c++) {
        size_t p = base + c;
        float wgt = __expf(g_pm[p * 64 + hq] - M);
        L += g_pl[p * 64 + hq] * wgt;
        A += g_pacc[(p * 64 + hq) * 128 + d] * wgt;
    }
    int t = w * 16 + q;
    g_attn[(size_t)t * 4096 + h * 128 + d] = A / L;
}

// ----------------------------- launch ---------------------------------------
extern "C" void kernel_launch(void* const* d_in, const int* in_sizes, int n_in,
                              void* d_out, int out_size) {
    const float* hs   = (const float*)d_in[0];
    const float* Wq   = (const float*)d_in[1];
    const float* bq   = (const float*)d_in[2];
    const float* Wk   = (const float*)d_in[3];
    const float* bk   = (const float*)d_in[4];
    const float* Wv   = (const float*)d_in[5];
    const float* bv   = (const float*)d_in[6];
    const float* Wo   = (const float*)d_in[7];
    const float* ssk  = (const float*)d_in[8];
    const float* ssv  = (const float*)d_in[9];
    const float* w0k  = (const float*)d_in[10];
    const float* w0v  = (const float*)d_in[11];
    const float* w1k  = (const float*)d_in[12];
    const float* w1v  = (const float*)d_in[13];
    const float* cosn = (const float*)d_in[14];
    const float* sinn = (const float*)d_in[15];
    float* out = (float*)d_out;

    cudaFuncSetAttribute(attn_kernel,
                         cudaFuncAttributeMaxDynamicSharedMemorySize, 198656);

    qcs_kernel<<<96, 64>>>();

    // QKV projection, k-split 8 (KC=512)
    gemm_kernel<<<dim3(32, 8), 256>>>(hs, Wq, 0, 0, 6144, 0,    4096, 512);
    gemm_kernel<<<dim3(8, 8),  256>>>(hs, Wk, 0, 0, 6144, 4096, 4096, 512);
    gemm_kernel<<<dim3(8, 8),  256>>>(hs, Wv, 0, 0, 6144, 5120, 4096, 512);
    reduce_qkv_kernel<<<768, 256>>>(bq, bk, bv);

    rope_q_kernel<<<3072, 128>>>();
    rope_kv_kernel<<<256, 128>>>(cosn, sinn);

    attn_kernel<<<dim3(98, 16), 256, 198656>>>(ssk, ssv, w0k, w0v, w1k, w1v);
    combine_kernel<<<1024, 128>>>();

    // O projection
    gemm_kernel<<<dim3(32, 8), 256>>>(nullptr, Wo, 1, 1, 4096, 0, 4096, 512);
    reduce_out_kernel<<<512, 256>>>(out);
}

// round 10
// speedup vs baseline: 1.2101x; 1.2101x over previous
#include <cuda_runtime.h>
#include <cuda_bf16.h>
#include <math.h>

typedef unsigned long long ull;

#define SCALE 0.08838834764831843f

// ----------------------------- device scratch -------------------------------
__device__ float  g_qkvp[16 * 32 * 6144];         // k-split partials (QKV)
__device__ float  g_qkv [32 * 6144];              // reduced qkv + bias
__device__ float  g_rqdup[3 * 2 * 32 * 16 * 256]; // roped q, 3 pos-sets, duplicated pairs
__device__ float  g_knew[2 * 8 * 16 * 128];       // roped new keys
__device__ float  g_vnew[2 * 8 * 16 * 128];       // new values
__device__ float  g_pm [16 * 98 * 64];            // split-K partial max
__device__ float  g_pl [16 * 98 * 64];            // split-K partial sum
__device__ float  g_pacc[16 * 98 * 64 * 128];     // split-K partial accum
__device__ float  g_attn[32 * 4096];              // attention out, tokens x (H*D)
__device__ float  g_op [16 * 32 * 4096];          // k-split partials (O proj)
__device__ float2 g_qcs[3 * 2 * 16 * 64];         // q-rope cos/sin table

// ----------------------------- f32x2 helpers --------------------------------
__device__ __forceinline__ ull ffma2(ull a, ull b, ull c) {
    ull d;
    asm("fma.rn.f32x2 %0, %1, %2, %3;" : "=l"(d) : "l"(a), "l"(b), "l"(c));
    return d;
}
__device__ __forceinline__ ull pk2(float x, float y) {
    ull r;
    asm("mov.b64 %0, {%1, %2};" : "=l"(r) : "f"(x), "f"(y));
    return r;
}
__device__ __forceinline__ float2 unpk(ull v) {
    float2 r;
    asm("mov.b64 {%0, %1}, %2;" : "=f"(r.x), "=f"(r.y) : "l"(v));
    return r;
}

// ----------------------------- rope tables ----------------------------------
// loc bases: seg0: 12304 both; seg1: w0->2048, w1->4112; seg2: w0->4112, w1->2048
__global__ void qcs_kernel() {
    int j  = threadIdx.x;          // 0..63
    int b  = blockIdx.x;           // 0..95
    int qi = b & 15;
    int w  = (b >> 4) & 1;
    int seg = b >> 5;
    int base = (seg == 0) ? 12304 : (seg == 1) ? ((w == 0) ? 2048 : 4112)
                                               : ((w == 0) ? 4112 : 2048);
    double inv = exp(-(double)j * 0.14391156831212787);   // ln(10000)/64
    float invf = (float)inv;
    float angf = (float)(base + qi) * invf;               // f32 rounding like reference
    double ang = (double)angf;
    g_qcs[((seg * 2 + w) * 16 + qi) * 64 + j] =
        make_float2((float)cos(ang), (float)sin(ang));
}

__global__ void rope_q_kernel() {
    int d  = threadIdx.x;
    int b  = blockIdx.x;
    int qi = b & 15;
    int h  = (b >> 4) & 31;
    int w  = (b >> 9) & 1;
    int seg = b >> 10;
    int t = w * 16 + qi;
    float qv  = g_qkv[t * 6144 + h * 128 + d];
    float rot = (d < 64) ? -g_qkv[t * 6144 + h * 128 + d + 64]
                         :  g_qkv[t * 6144 + h * 128 + d - 64];
    float2 cs = g_qcs[((seg * 2 + w) * 16 + qi) * 64 + (d & 63)];
    float r = qv * cs.x + rot * cs.y;
    size_t o = ((size_t)(((seg * 2 + w) * 32 + h) * 16 + qi)) * 256 + 2 * d;
    g_rqdup[o] = r;
    g_rqdup[o + 1] = r;
}

__global__ void rope_kv_kernel(const float* __restrict__ cosn,
                               const float* __restrict__ sinn) {
    int d  = threadIdx.x;
    int b  = blockIdx.x;
    int qi = b & 15;
    int kv = (b >> 4) & 7;
    int w  = b >> 7;
    int t = w * 16 + qi;
    float c = cosn[(w * 16 + qi) * 128 + d];
    float s = sinn[(w * 16 + qi) * 128 + d];
    float k   = g_qkv[t * 6144 + 4096 + kv * 128 + d];
    float rot = (d < 64) ? -g_qkv[t * 6144 + 4096 + kv * 128 + d + 64]
                         :  g_qkv[t * 6144 + 4096 + kv * 128 + d - 64];
    int o = ((w * 8 + kv) * 16 + qi) * 128 + d;
    g_knew[o] = k * c + rot * s;
    g_vnew[o] = g_qkv[t * 6144 + 5120 + kv * 128 + d];
}

// ----------------------------- GEMM body ------------------------------------
// C[t][o] = sum_k A[t][k]*W[o][k]; k-split partials at g (per blockIdx.y).
__device__ __forceinline__ void gemm_body(
    const float* __restrict__ A, const float* __restrict__ W,
    float* __restrict__ Cp, int ldC, int colOff, int K, int KC, int o0) {
    __shared__ float As[64][34];
    __shared__ float Ws[64][132];

    int tid = threadIdx.x;
    int kb  = blockIdx.y * KC;
    int to  = tid & 31;
    int tt  = tid >> 5;

    ull c2[4][2];
#pragma unroll
    for (int i = 0; i < 4; i++) { c2[i][0] = 0ULL; c2[i][1] = 0ULL; }

    for (int kk = 0; kk < KC; kk += 64) {
#pragma unroll
        for (int r = 0; r < 2; r++) {
            int f = tid + r * 256;
            int t = f & 31, kq = f >> 5;
            float4 av = *(const float4*)&A[(size_t)t * K + kb + kk + 4 * kq];
            As[4 * kq + 0][t] = av.x;
            As[4 * kq + 1][t] = av.y;
            As[4 * kq + 2][t] = av.z;
            As[4 * kq + 3][t] = av.w;
        }
#pragma unroll
        for (int r = 0; r < 8; r++) {
            int f = tid + r * 256;
            int o = f & 127, kq = f >> 7;
            float4 wv = *(const float4*)&W[(size_t)(o0 + o) * K + kb + kk + 4 * kq];
            Ws[4 * kq + 0][o] = wv.x;
            Ws[4 * kq + 1][o] = wv.y;
            Ws[4 * kq + 2][o] = wv.z;
            Ws[4 * kq + 3][o] = wv.w;
        }
        __syncthreads();
#pragma unroll 8
        for (int k = 0; k < 64; k++) {
            ull a0 = *(const ull*)&As[k][4 * tt];
            ull a1 = *(const ull*)&As[k][4 * tt + 2];
            float4 wv = *(const float4*)&Ws[k][4 * to];
            ull w0 = pk2(wv.x, wv.x), w1 = pk2(wv.y, wv.y);
            ull w2 = pk2(wv.z, wv.z), w3 = pk2(wv.w, wv.w);
            c2[0][0] = ffma2(w0, a0, c2[0][0]); c2[0][1] = ffma2(w0, a1, c2[0][1]);
            c2[1][0] = ffma2(w1, a0, c2[1][0]); c2[1][1] = ffma2(w1, a1, c2[1][1]);
            c2[2][0] = ffma2(w2, a0, c2[2][0]); c2[2][1] = ffma2(w2, a1, c2[2][1]);
            c2[3][0] = ffma2(w3, a0, c2[3][0]); c2[3][1] = ffma2(w3, a1, c2[3][1]);
        }
        __syncthreads();
    }
    int ks = blockIdx.y;
#pragma unroll
    for (int i = 0; i < 4; i++) {
        int o = o0 + 4 * to + i;
#pragma unroll
        for (int p = 0; p < 2; p++) {
            float2 v = unpk(c2[i][p]);
            int t0 = 4 * tt + 2 * p;
            Cp[(size_t)(ks * 32 + t0) * ldC + colOff + o]     = v.x;
            Cp[(size_t)(ks * 32 + t0 + 1) * ldC + colOff + o] = v.y;
        }
    }
}

__global__ __launch_bounds__(256) void qkv_gemm_kernel(
    const float* __restrict__ A, const float* __restrict__ Wq,
    const float* __restrict__ Wk, const float* __restrict__ Wv) {
    int bx = blockIdx.x;
    const float* W; int o0, colOff;
    if (bx < 32)      { W = Wq; o0 = bx * 128;        colOff = 0;    }
    else if (bx < 40) { W = Wk; o0 = (bx - 32) * 128; colOff = 4096; }
    else              { W = Wv; o0 = (bx - 40) * 128; colOff = 5120; }
    gemm_body(A, W, g_qkvp, 6144, colOff, 4096, 256, o0);
}

__global__ __launch_bounds__(256) void o_gemm_kernel(const float* __restrict__ Wo) {
    gemm_body(g_attn, Wo, g_op, 4096, 0, 4096, 256, blockIdx.x * 128);
}

__global__ void reduce_qkv_kernel(const float* __restrict__ bq,
                                  const float* __restrict__ bk,
                                  const float* __restrict__ bv) {
    int idx = blockIdx.x * 256 + threadIdx.x;   // < 196608
    float s = 0.f;
#pragma unroll
    for (int ks = 0; ks < 16; ks++) s += g_qkvp[(size_t)ks * 196608 + idx];
    int o = idx % 6144;
    float b = (o < 4096) ? bq[o] : (o < 5120 ? bk[o - 4096] : bv[o - 5120]);
    g_qkv[idx] = s + b;
}

__global__ void reduce_out_kernel(float* __restrict__ out) {
    int idx = blockIdx.x * 256 + threadIdx.x;   // < 131072
    float s = 0.f;
#pragma unroll
    for (int ks = 0; ks < 16; ks++) s += g_op[(size_t)ks * 131072 + idx];
    out[idx] = s;
}

// ----------------------------- attention ------------------------------------
// grid (98, 16=w*8+kv), 512 threads, 192KB dynamic smem.
// smem: KT2/V2 cells [0,16384); SC dup [16384,32768); RQ dup [32768,49152)
// KT2 cell(dp,lp) float4 = (K[2dp][2lp],K[2dp][2lp+1],K[2dp+1][2lp],K[2dp+1][2lp+1])
// V2  cell(lp,dp) float4 = (V[2lp][2dp],V[2lp][2dp+1],V[2lp+1][2dp],V[2lp+1][2dp+1])
__global__ __launch_bounds__(512) void attn_kernel(
    const float* __restrict__ ssk, const float* __restrict__ ssv,
    const float* __restrict__ w0k, const float* __restrict__ w0v,
    const float* __restrict__ w1k, const float* __restrict__ w1v) {
    extern __shared__ float sm[];
    float* KV = sm;
    float* SC = sm + 16384;
    float* RQ = sm + 32768;
    __shared__ float redm[64][8], redl[64][8], mfin[64];

    int tid = threadIdx.x;
    int cid = blockIdx.x, wkv = blockIdx.y;
    int w = wkv >> 3, kv = wkv & 7;

    int seg, nl = 128, ownnew = 0;
    const float *ksrc, *vsrc;
    if (cid < 64) {
        seg = 0;
        size_t off = ((size_t)kv * 8192 + cid * 128) * 128;
        ksrc = ssk + off; vsrc = ssv + off;
    } else if (cid < 81) {
        seg = 1;
        int cc = cid - 64;
        if (cc < 16) {
            size_t off = ((size_t)kv * 2048 + cc * 128) * 128;
            ksrc = w0k + off; vsrc = w0v + off;
        } else {
            nl = 16; ownnew = (w == 0);
            size_t off = (size_t)kv * 16 * 128;
            ksrc = g_knew + off; vsrc = g_vnew + off;
        }
    } else {
        seg = 2;
        int cc = cid - 81;
        if (cc < 16) {
            size_t off = ((size_t)kv * 2048 + cc * 128) * 128;
            ksrc = w1k + off; vsrc = w1v + off;
        } else {
            nl = 16; ownnew = (w == 1);
            size_t off = (size_t)(8 + kv) * 16 * 128;
            ksrc = g_knew + off; vsrc = g_vnew + off;
        }
    }
    int pidx = wkv * 98 + cid;

    // ---- load RQ (dup) for the 4 heads of this kv ----
    {
        const float4* s4 = (const float4*)(g_rqdup +
            (size_t)((seg * 2 + w) * 32 + kv * 4) * 16 * 256);
        float4* d4 = (float4*)RQ;
#pragma unroll
        for (int r = 0; r < 8; r++) d4[tid + r * 512] = s4[tid + r * 512];
    }
    // ---- load K into KT2 cells ----
#pragma unroll
    for (int r = 0; r < 8; r++) {
        int f = tid + r * 512;
        int l = f & 127, dq = f >> 7;        // dq 0..31 (4 dims each)
        float4 v = (l < nl) ? ((const float4*)ksrc)[l * 32 + dq]
                            : make_float4(0.f, 0.f, 0.f, 0.f);
        int lp = l >> 1, h = l & 1;
        int b0 = (2 * dq * 64 + lp) * 4, b1 = ((2 * dq + 1) * 64 + lp) * 4;
        KV[b0 + h]     = v.x;
        KV[b0 + 2 + h] = v.y;
        KV[b1 + h]     = v.z;
        KV[b1 + 2 + h] = v.w;
    }
    __syncthreads();

    int lane = tid & 31, wi = tid >> 5;
    int hh = wi & 3, q0 = (wi >> 2) * 4;      // head, q-quarter

    // ---- QK: warp=(head,q-quarter); lane owns keys {2lane,2lane+1,2lane+64,2lane+65}
    {
        ull acc[4][2];
#pragma unroll
        for (int q = 0; q < 4; q++) { acc[q][0] = 0ULL; acc[q][1] = 0ULL; }
        const float* rqh = RQ + (hh * 16 + q0) * 256;
#pragma unroll 4
        for (int dp = 0; dp < 64; dp++) {
            ulonglong2 c0 = *(const ulonglong2*)&KV[(dp * 64 + lane) * 4];
            ulonglong2 c1 = *(const ulonglong2*)&KV[(dp * 64 + lane + 32) * 4];
#pragma unroll
            for (int q = 0; q < 4; q++) {
                ulonglong2 r = *(const ulonglong2*)&rqh[q * 256 + 4 * dp];
                acc[q][0] = ffma2(r.x, c0.x, acc[q][0]);
                acc[q][0] = ffma2(r.y, c0.y, acc[q][0]);
                acc[q][1] = ffma2(r.x, c1.x, acc[q][1]);
                acc[q][1] = ffma2(r.y, c1.y, acc[q][1]);
            }
        }
        int kA = 2 * lane, kB = 2 * lane + 64;
#pragma unroll
        for (int q = 0; q < 4; q++) {
            int qg = q0 + q;
            float2 sA = unpk(acc[q][0]);
            float2 sB = unpk(acc[q][1]);
            float a0 = ((kA     < nl) && (!ownnew || kA     <= qg)) ? sA.x * SCALE : -1e30f;
            float a1 = ((kA + 1 < nl) && (!ownnew || kA + 1 <= qg)) ? sA.y * SCALE : -1e30f;
            float b0 = ((kB     < nl) && (!ownnew || kB     <= qg)) ? sB.x * SCALE : -1e30f;
            float b1 = ((kB + 1 < nl) && (!ownnew || kB + 1 <= qg)) ? sB.y * SCALE : -1e30f;
            *(float4*)&SC[(hh * 16 + qg) * 256 + 4 * lane]       = make_float4(a0, a0, a1, a1);
            *(float4*)&SC[(hh * 16 + qg) * 256 + 128 + 4 * lane] = make_float4(b0, b0, b1, b1);
        }
    }
    __syncthreads();

    // ---- load V into V2 cells (reuse KV region; QK done) ----
#pragma unroll
    for (int r = 0; r < 8; r++) {
        int f = tid + r * 512;
        int l = f & 127, dq = f >> 7;
        float4 v = (l < nl) ? ((const float4*)vsrc)[l * 32 + dq]
                            : make_float4(0.f, 0.f, 0.f, 0.f);
        int lp = l >> 1, h2 = (l & 1) * 2;
        *(float2*)&KV[(lp * 64 + 2 * dq) * 4 + h2]     = make_float2(v.x, v.y);
        *(float2*)&KV[(lp * 64 + 2 * dq + 1) * 4 + h2] = make_float2(v.z, v.w);
    }

    // ---- per-chunk softmax over SC (dup entries) ----
    {
        int hq = tid & 63, part = tid >> 6;   // 8 parts x 16 keys
        float* row = SC + hq * 256;
        float m = -1e30f;
#pragma unroll
        for (int i = 0; i < 16; i++) m = fmaxf(m, row[2 * (part * 16 + i)]);
        redm[hq][part] = m;
        __syncthreads();
        if (tid < 64) {
            float mm = redm[tid][0];
#pragma unroll
            for (int p = 1; p < 8; p++) mm = fmaxf(mm, redm[tid][p]);
            mfin[tid] = mm;
        }
        __syncthreads();
        float mm = mfin[hq];
        float s = 0.f;
#pragma unroll
        for (int i = 0; i < 16; i++) {
            int idx = 2 * (part * 16 + i);
            float p = __expf(row[idx] - mm);
            row[idx] = p; row[idx + 1] = p;
            s += p;
        }
        redl[hq][part] = s;
        __syncthreads();
        if (tid < 64) {
            float L = 0.f;
#pragma unroll
            for (int p = 0; p < 8; p++) L += redl[tid][p];
            g_pm[(size_t)pidx * 64 + tid] = mfin[tid];
            g_pl[(size_t)pidx * 64 + tid] = L;
        }
        __syncthreads();   // probs + V both ready
    }

    // ---- PV: warp=(head,q-quarter); lane owns dims {2lane,2lane+1,2lane+64,2lane+65}
    {
        ull acc[4][2];
#pragma unroll
        for (int q = 0; q < 4; q++) { acc[q][0] = 0ULL; acc[q][1] = 0ULL; }
        const float* sch = SC + (hh * 16 + q0) * 256;
#pragma unroll 4
        for (int lp = 0; lp < 64; lp++) {
            ulonglong2 v0 = *(const ulonglong2*)&KV[(lp * 64 + lane) * 4];
            ulonglong2 v1 = *(const ulonglong2*)&KV[(lp * 64 + lane + 32) * 4];
#pragma unroll
            for (int q = 0; q < 4; q++) {
                ulonglong2 p = *(const ulonglong2*)&sch[q * 256 + 4 * lp];
                acc[q][0] = ffma2(p.x, v0.x, acc[q][0]);
                acc[q][0] = ffma2(p.y, v0.y, acc[q][0]);
                acc[q][1] = ffma2(p.x, v1.x, acc[q][1]);
                acc[q][1] = ffma2(p.y, v1.y, acc[q][1]);
            }
        }
#pragma unroll
        for (int q = 0; q < 4; q++) {
            int qg = q0 + q;
            float2 a = unpk(acc[q][0]);
            float2 b = unpk(acc[q][1]);
            size_t base = ((size_t)pidx * 64 + hh * 16 + qg) * 128;
            *(float2*)&g_pacc[base + 2 * lane]      = a;
            *(float2*)&g_pacc[base + 2 * lane + 64] = b;
        }
    }
}

// split-K combine: grid 1024 = (w,h,q), 128 threads = d
__global__ __launch_bounds__(128) void combine_kernel() {
    int d = threadIdx.x;
    int b = blockIdx.x;
    int q = b & 15, h = (b >> 4) & 31, w = b >> 9;
    int kv = h >> 2;
    int hq = (h & 3) * 16 + q;
    size_t base = (size_t)(w * 8 + kv) * 98;
    float M = -1e30f;
    for (int c = 0; c < 98; c++) M = fmaxf(M, g_pm[(base + c) * 64 + hq]);
    float L = 0.f, A = 0.f;
    for (int c = 0; c < 98; c++) {
        size_t p = base + c;
        float wgt = __expf(g_pm[p * 64 + hq] - M);
        L += g_pl[p * 64 + hq] * wgt;
        A += g_pacc[(p * 64 + hq) * 128 + d] * wgt;
    }
    int t = w * 16 + q;
    g_attn[(size_t)t * 4096 + h * 128 + d] = A / L;
}

// ----------------------------- launch ---------------------------------------
extern "C" void kernel_launch(void* const* d_in, const int* in_sizes, int n_in,
                              void* d_out, int out_size) {
    const float* hs   = (const float*)d_in[0];
    const float* Wq   = (const float*)d_in[1];
    const float* bq   = (const float*)d_in[2];
    const float* Wk   = (const float*)d_in[3];
    const float* bk   = (const float*)d_in[4];
    const float* Wv   = (const float*)d_in[5];
    const float* bv   = (const float*)d_in[6];
    const float* Wo   = (const float*)d_in[7];
    const float* ssk  = (const float*)d_in[8];
    const float* ssv  = (const float*)d_in[9];
    const float* w0k  = (const float*)d_in[10];
    const float* w0v  = (const float*)d_in[11];
    const float* w1k  = (const float*)d_in[12];
    const float* w1v  = (const float*)d_in[13];
    const float* cosn = (const float*)d_in[14];
    const float* sinn = (const float*)d_in[15];
    float* out = (float*)d_out;

    cudaFuncSetAttribute(attn_kernel,
                         cudaFuncAttributeMaxDynamicSharedMemorySize, 196608);

    qcs_kernel<<<96, 64>>>();

    qkv_gemm_kernel<<<dim3(48, 16), 256>>>(hs, Wq, Wk, Wv);
    reduce_qkv_kernel<<<768, 256>>>(bq, bk, bv);

    rope_q_kernel<<<3072, 128>>>();
    rope_kv_kernel<<<256, 128>>>(cosn, sinn);

    attn_kernel<<<dim3(98, 16), 512, 196608>>>(ssk, ssv, w0k, w0v, w1k, w1v);
    combine_kernel<<<1024, 128>>>();

    o_gemm_kernel<<<dim3(32, 16), 256>>>(Wo);
    reduce_out_kernel<<<512, 256>>>(out);
}

// round 11
// speedup vs baseline: 1.3086x; 1.0814x over previous
#include <cuda_runtime.h>
#include <cuda_bf16.h>
#include <math.h>

typedef unsigned long long ull;

#define SCALE 0.08838834764831843f

// ----------------------------- device scratch -------------------------------
__device__ float  g_qkvp[16 * 32 * 6144];         // k-split partials (QKV)
__device__ float  g_qkv [32 * 6144];              // reduced qkv + bias
__device__ float  g_rqdup[3 * 2 * 32 * 16 * 256]; // roped q, 3 pos-sets, duplicated pairs
__device__ float  g_knew[2 * 8 * 16 * 128];       // roped new keys
__device__ float  g_vnew[2 * 8 * 16 * 128];       // new values
__device__ float  g_pm [16 * 98 * 64];            // split-K partial max
__device__ float  g_pl [16 * 98 * 64];            // split-K partial sum
__device__ float  g_pacc[16 * 98 * 64 * 128];     // split-K partial accum
__device__ float  g_attn[32 * 4096];              // attention out, tokens x (H*D)
__device__ float  g_op [16 * 32 * 4096];          // k-split partials (O proj)
__device__ float2 g_qcs[3 * 2 * 16 * 64];         // q-rope cos/sin table

// ----------------------------- f32x2 helpers --------------------------------
__device__ __forceinline__ ull ffma2(ull a, ull b, ull c) {
    ull d;
    asm("fma.rn.f32x2 %0, %1, %2, %3;" : "=l"(d) : "l"(a), "l"(b), "l"(c));
    return d;
}
__device__ __forceinline__ ull pk2(float x, float y) {
    ull r;
    asm("mov.b64 %0, {%1, %2};" : "=l"(r) : "f"(x), "f"(y));
    return r;
}
__device__ __forceinline__ float2 unpk(ull v) {
    float2 r;
    asm("mov.b64 {%0, %1}, %2;" : "=f"(r.x), "=f"(r.y) : "l"(v));
    return r;
}

// ----------------------------- rope tables ----------------------------------
// loc bases: seg0: 12304 both; seg1: w0->2048, w1->4112; seg2: w0->4112, w1->2048
__global__ void qcs_kernel() {
    int j  = threadIdx.x;          // 0..63
    int b  = blockIdx.x;           // 0..95
    int qi = b & 15;
    int w  = (b >> 4) & 1;
    int seg = b >> 5;
    int base = (seg == 0) ? 12304 : (seg == 1) ? ((w == 0) ? 2048 : 4112)
                                               : ((w == 0) ? 4112 : 2048);
    double inv = exp(-(double)j * 0.14391156831212787);   // ln(10000)/64
    float invf = (float)inv;
    float angf = (float)(base + qi) * invf;               // f32 rounding like reference
    double ang = (double)angf;
    g_qcs[((seg * 2 + w) * 16 + qi) * 64 + j] =
        make_float2((float)cos(ang), (float)sin(ang));
}

__global__ void rope_q_kernel() {
    int d  = threadIdx.x;
    int b  = blockIdx.x;
    int qi = b & 15;
    int h  = (b >> 4) & 31;
    int w  = (b >> 9) & 1;
    int seg = b >> 10;
    int t = w * 16 + qi;
    float qv  = g_qkv[t * 6144 + h * 128 + d];
    float rot = (d < 64) ? -g_qkv[t * 6144 + h * 128 + d + 64]
                         :  g_qkv[t * 6144 + h * 128 + d - 64];
    float2 cs = g_qcs[((seg * 2 + w) * 16 + qi) * 64 + (d & 63)];
    float r = qv * cs.x + rot * cs.y;
    size_t o = ((size_t)(((seg * 2 + w) * 32 + h) * 16 + qi)) * 256 + 2 * d;
    g_rqdup[o] = r;
    g_rqdup[o + 1] = r;
}

__global__ void rope_kv_kernel(const float* __restrict__ cosn,
                               const float* __restrict__ sinn) {
    int d  = threadIdx.x;
    int b  = blockIdx.x;
    int qi = b & 15;
    int kv = (b >> 4) & 7;
    int w  = b >> 7;
    int t = w * 16 + qi;
    float c = cosn[(w * 16 + qi) * 128 + d];
    float s = sinn[(w * 16 + qi) * 128 + d];
    float k   = g_qkv[t * 6144 + 4096 + kv * 128 + d];
    float rot = (d < 64) ? -g_qkv[t * 6144 + 4096 + kv * 128 + d + 64]
                         :  g_qkv[t * 6144 + 4096 + kv * 128 + d - 64];
    int o = ((w * 8 + kv) * 16 + qi) * 128 + d;
    g_knew[o] = k * c + rot * s;
    g_vnew[o] = g_qkv[t * 6144 + 5120 + kv * 128 + d];
}

// ----------------------------- GEMM body ------------------------------------
__device__ __forceinline__ void gemm_body(
    const float* __restrict__ A, const float* __restrict__ W,
    float* __restrict__ Cp, int ldC, int colOff, int K, int KC, int o0) {
    __shared__ float As[64][34];
    __shared__ float Ws[64][132];

    int tid = threadIdx.x;
    int kb  = blockIdx.y * KC;
    int to  = tid & 31;
    int tt  = tid >> 5;

    ull c2[4][2];
#pragma unroll
    for (int i = 0; i < 4; i++) { c2[i][0] = 0ULL; c2[i][1] = 0ULL; }

    for (int kk = 0; kk < KC; kk += 64) {
#pragma unroll
        for (int r = 0; r < 2; r++) {
            int f = tid + r * 256;
            int t = f & 31, kq = f >> 5;
            float4 av = *(const float4*)&A[(size_t)t * K + kb + kk + 4 * kq];
            As[4 * kq + 0][t] = av.x;
            As[4 * kq + 1][t] = av.y;
            As[4 * kq + 2][t] = av.z;
            As[4 * kq + 3][t] = av.w;
        }
#pragma unroll
        for (int r = 0; r < 8; r++) {
            int f = tid + r * 256;
            int o = f & 127, kq = f >> 7;
            float4 wv = *(const float4*)&W[(size_t)(o0 + o) * K + kb + kk + 4 * kq];
            Ws[4 * kq + 0][o] = wv.x;
            Ws[4 * kq + 1][o] = wv.y;
            Ws[4 * kq + 2][o] = wv.z;
            Ws[4 * kq + 3][o] = wv.w;
        }
        __syncthreads();
#pragma unroll 8
        for (int k = 0; k < 64; k++) {
            ull a0 = *(const ull*)&As[k][4 * tt];
            ull a1 = *(const ull*)&As[k][4 * tt + 2];
            float4 wv = *(const float4*)&Ws[k][4 * to];
            ull w0 = pk2(wv.x, wv.x), w1 = pk2(wv.y, wv.y);
            ull w2 = pk2(wv.z, wv.z), w3 = pk2(wv.w, wv.w);
            c2[0][0] = ffma2(w0, a0, c2[0][0]); c2[0][1] = ffma2(w0, a1, c2[0][1]);
            c2[1][0] = ffma2(w1, a0, c2[1][0]); c2[1][1] = ffma2(w1, a1, c2[1][1]);
            c2[2][0] = ffma2(w2, a0, c2[2][0]); c2[2][1] = ffma2(w2, a1, c2[2][1]);
            c2[3][0] = ffma2(w3, a0, c2[3][0]); c2[3][1] = ffma2(w3, a1, c2[3][1]);
        }
        __syncthreads();
    }
    int ks = blockIdx.y;
#pragma unroll
    for (int i = 0; i < 4; i++) {
        int o = o0 + 4 * to + i;
#pragma unroll
        for (int p = 0; p < 2; p++) {
            float2 v = unpk(c2[i][p]);
            int t0 = 4 * tt + 2 * p;
            Cp[(size_t)(ks * 32 + t0) * ldC + colOff + o]     = v.x;
            Cp[(size_t)(ks * 32 + t0 + 1) * ldC + colOff + o] = v.y;
        }
    }
}

__global__ __launch_bounds__(256) void qkv_gemm_kernel(
    const float* __restrict__ A, const float* __restrict__ Wq,
    const float* __restrict__ Wk, const float* __restrict__ Wv) {
    int bx = blockIdx.x;
    const float* W; int o0, colOff;
    if (bx < 32)      { W = Wq; o0 = bx * 128;        colOff = 0;    }
    else if (bx < 40) { W = Wk; o0 = (bx - 32) * 128; colOff = 4096; }
    else              { W = Wv; o0 = (bx - 40) * 128; colOff = 5120; }
    gemm_body(A, W, g_qkvp, 6144, colOff, 4096, 256, o0);
}

__global__ __launch_bounds__(256) void o_gemm_kernel(const float* __restrict__ Wo) {
    gemm_body(g_attn, Wo, g_op, 4096, 0, 4096, 256, blockIdx.x * 128);
}

__global__ void reduce_qkv_kernel(const float* __restrict__ bq,
                                  const float* __restrict__ bk,
                                  const float* __restrict__ bv) {
    int idx = blockIdx.x * 256 + threadIdx.x;   // < 196608
    float s = 0.f;
#pragma unroll
    for (int ks = 0; ks < 16; ks++) s += g_qkvp[(size_t)ks * 196608 + idx];
    int o = idx % 6144;
    float b = (o < 4096) ? bq[o] : (o < 5120 ? bk[o - 4096] : bv[o - 5120]);
    g_qkv[idx] = s + b;
}

__global__ void reduce_out_kernel(float* __restrict__ out) {
    int idx = blockIdx.x * 256 + threadIdx.x;   // < 131072
    float s = 0.f;
#pragma unroll
    for (int ks = 0; ks < 16; ks++) s += g_op[(size_t)ks * 131072 + idx];
    out[idx] = s;
}

// ----------------------------- attention ------------------------------------
// grid (98, 16=w*8+kv), 256 threads, 192KB dynamic smem.
// 8 warps = 4 heads x 2 q-halves; each warp: 8 q x 128 keys (QK) / 128 dims (PV).
// KT2 cell(dp,lp) float4 = (K[2dp][2lp],K[2dp][2lp+1],K[2dp+1][2lp],K[2dp+1][2lp+1])
// V2  cell(lp,dp) float4 = (V[2lp][2dp],V[2lp][2dp+1],V[2lp+1][2dp],V[2lp+1][2dp+1])
__global__ __launch_bounds__(256) void attn_kernel(
    const float* __restrict__ ssk, const float* __restrict__ ssv,
    const float* __restrict__ w0k, const float* __restrict__ w0v,
    const float* __restrict__ w1k, const float* __restrict__ w1v) {
    extern __shared__ float sm[];
    float* KV = sm;
    float* SC = sm + 16384;
    float* RQ = sm + 32768;
    __shared__ float redm[64][4], redl[64][4], mfin[64];

    int tid = threadIdx.x;
    int cid = blockIdx.x, wkv = blockIdx.y;
    int w = wkv >> 3, kv = wkv & 7;

    int seg, nl = 128, ownnew = 0;
    const float *ksrc, *vsrc;
    if (cid < 64) {
        seg = 0;
        size_t off = ((size_t)kv * 8192 + cid * 128) * 128;
        ksrc = ssk + off; vsrc = ssv + off;
    } else if (cid < 81) {
        seg = 1;
        int cc = cid - 64;
        if (cc < 16) {
            size_t off = ((size_t)kv * 2048 + cc * 128) * 128;
            ksrc = w0k + off; vsrc = w0v + off;
        } else {
            nl = 16; ownnew = (w == 0);
            size_t off = (size_t)kv * 16 * 128;
            ksrc = g_knew + off; vsrc = g_vnew + off;
        }
    } else {
        seg = 2;
        int cc = cid - 81;
        if (cc < 16) {
            size_t off = ((size_t)kv * 2048 + cc * 128) * 128;
            ksrc = w1k + off; vsrc = w1v + off;
        } else {
            nl = 16; ownnew = (w == 1);
            size_t off = (size_t)(8 + kv) * 16 * 128;
            ksrc = g_knew + off; vsrc = g_vnew + off;
        }
    }
    int pidx = wkv * 98 + cid;

    // ---- load RQ (dup) for the 4 heads of this kv ----
    {
        const float4* s4 = (const float4*)(g_rqdup +
            (size_t)((seg * 2 + w) * 32 + kv * 4) * 16 * 256);
        float4* d4 = (float4*)RQ;
#pragma unroll
        for (int r = 0; r < 16; r++) d4[tid + r * 256] = s4[tid + r * 256];
    }
    // ---- load K into KT2 cells ----
#pragma unroll
    for (int r = 0; r < 16; r++) {
        int f = tid + r * 256;
        int l = f & 127, dq = f >> 7;        // dq 0..31 (4 dims each)
        float4 v = (l < nl) ? ((const float4*)ksrc)[l * 32 + dq]
                            : make_float4(0.f, 0.f, 0.f, 0.f);
        int lp = l >> 1, h = l & 1;
        int b0 = (2 * dq * 64 + lp) * 4, b1 = ((2 * dq + 1) * 64 + lp) * 4;
        KV[b0 + h]     = v.x;
        KV[b0 + 2 + h] = v.y;
        KV[b1 + h]     = v.z;
        KV[b1 + 2 + h] = v.w;
    }
    __syncthreads();

    int lane = tid & 31, wi = tid >> 5;
    int hh = wi & 3, q0 = (wi >> 2) * 8;      // head, q-half

    // ---- QK: warp=(head,q-half); lane owns keys {2lane,2lane+1,2lane+64,2lane+65}
    {
        ull acc[8][2];
#pragma unroll
        for (int q = 0; q < 8; q++) { acc[q][0] = 0ULL; acc[q][1] = 0ULL; }
        const float* rqh = RQ + (hh * 16 + q0) * 256;
#pragma unroll 2
        for (int dp = 0; dp < 64; dp++) {
            ulonglong2 c0 = *(const ulonglong2*)&KV[(dp * 64 + lane) * 4];
            ulonglong2 c1 = *(const ulonglong2*)&KV[(dp * 64 + lane + 32) * 4];
#pragma unroll
            for (int q = 0; q < 8; q++) {
                ulonglong2 r = *(const ulonglong2*)&rqh[q * 256 + 4 * dp];
                acc[q][0] = ffma2(r.x, c0.x, acc[q][0]);
                acc[q][0] = ffma2(r.y, c0.y, acc[q][0]);
                acc[q][1] = ffma2(r.x, c1.x, acc[q][1]);
                acc[q][1] = ffma2(r.y, c1.y, acc[q][1]);
            }
        }
        int kA = 2 * lane, kB = 2 * lane + 64;
#pragma unroll
        for (int q = 0; q < 8; q++) {
            int qg = q0 + q;
            float2 sA = unpk(acc[q][0]);
            float2 sB = unpk(acc[q][1]);
            float a0 = ((kA     < nl) && (!ownnew || kA     <= qg)) ? sA.x * SCALE : -1e30f;
            float a1 = ((kA + 1 < nl) && (!ownnew || kA + 1 <= qg)) ? sA.y * SCALE : -1e30f;
            float b0 = ((kB     < nl) && (!ownnew || kB     <= qg)) ? sB.x * SCALE : -1e30f;
            float b1 = ((kB + 1 < nl) && (!ownnew || kB + 1 <= qg)) ? sB.y * SCALE : -1e30f;
            *(float4*)&SC[(hh * 16 + qg) * 256 + 4 * lane]       = make_float4(a0, a0, a1, a1);
            *(float4*)&SC[(hh * 16 + qg) * 256 + 128 + 4 * lane] = make_float4(b0, b0, b1, b1);
        }
    }
    __syncthreads();

    // ---- load V into V2 cells (reuse KV region; QK done) ----
#pragma unroll
    for (int r = 0; r < 16; r++) {
        int f = tid + r * 256;
        int l = f & 127, dq = f >> 7;
        float4 v = (l < nl) ? ((const float4*)vsrc)[l * 32 + dq]
                            : make_float4(0.f, 0.f, 0.f, 0.f);
        int lp = l >> 1, h2 = (l & 1) * 2;
        *(float2*)&KV[(lp * 64 + 2 * dq) * 4 + h2]     = make_float2(v.x, v.y);
        *(float2*)&KV[(lp * 64 + 2 * dq + 1) * 4 + h2] = make_float2(v.z, v.w);
    }

    // ---- per-chunk softmax over SC (dup entries) ----
    {
        int hq = tid & 63, part = tid >> 6;   // 4 parts x 32 keys
        float* row = SC + hq * 256;
        float m = -1e30f;
#pragma unroll
        for (int i = 0; i < 32; i++) m = fmaxf(m, row[2 * (part * 32 + i)]);
        redm[hq][part] = m;
        __syncthreads();
        if (tid < 64) {
            mfin[tid] = fmaxf(fmaxf(redm[tid][0], redm[tid][1]),
                              fmaxf(redm[tid][2], redm[tid][3]));
        }
        __syncthreads();
        float mm = mfin[hq];
        float s = 0.f;
#pragma unroll
        for (int i = 0; i < 32; i++) {
            int idx = 2 * (part * 32 + i);
            float p = __expf(row[idx] - mm);
            row[idx] = p; row[idx + 1] = p;
            s += p;
        }
        redl[hq][part] = s;
        __syncthreads();
        if (tid < 64) {
            float L = redl[tid][0] + redl[tid][1] + redl[tid][2] + redl[tid][3];
            g_pm[(size_t)pidx * 64 + tid] = mfin[tid];
            g_pl[(size_t)pidx * 64 + tid] = L;
        }
        __syncthreads();   // probs + V both ready
    }

    // ---- PV: warp=(head,q-half); lane owns dims {2lane,2lane+1,2lane+64,2lane+65}
    {
        ull acc[8][2];
#pragma unroll
        for (int q = 0; q < 8; q++) { acc[q][0] = 0ULL; acc[q][1] = 0ULL; }
        const float* sch = SC + (hh * 16 + q0) * 256;
#pragma unroll 2
        for (int lp = 0; lp < 64; lp++) {
            ulonglong2 v0 = *(const ulonglong2*)&KV[(lp * 64 + lane) * 4];
            ulonglong2 v1 = *(const ulonglong2*)&KV[(lp * 64 + lane + 32) * 4];
#pragma unroll
            for (int q = 0; q < 8; q++) {
                ulonglong2 p = *(const ulonglong2*)&sch[q * 256 + 4 * lp];
                acc[q][0] = ffma2(p.x, v0.x, acc[q][0]);
                acc[q][0] = ffma2(p.y, v0.y, acc[q][0]);
                acc[q][1] = ffma2(p.x, v1.x, acc[q][1]);
                acc[q][1] = ffma2(p.y, v1.y, acc[q][1]);
            }
        }
#pragma unroll
        for (int q = 0; q < 8; q++) {
            int qg = q0 + q;
            float2 a = unpk(acc[q][0]);
            float2 b = unpk(acc[q][1]);
            size_t base = ((size_t)pidx * 64 + hh * 16 + qg) * 128;
            *(float2*)&g_pacc[base + 2 * lane]      = a;
            *(float2*)&g_pacc[base + 2 * lane + 64] = b;
        }
    }
}

// split-K combine: grid 1024 = (w,h,q), 128 threads
__global__ __launch_bounds__(128) void combine_kernel() {
    __shared__ float swgt[98];
    __shared__ float redA[4], redB[4];
    int b = blockIdx.x;
    int q = b & 15, h = (b >> 4) & 31, w = b >> 9;
    int kv = h >> 2;
    int hq = (h & 3) * 16 + q;
    size_t base = (size_t)(w * 8 + kv) * 98;
    int tid = threadIdx.x;

    // phase 1: chunk-parallel M, L, weights
    float pm = (tid < 98) ? g_pm[(base + tid) * 64 + hq] : -3e38f;
    float pl = (tid < 98) ? g_pl[(base + tid) * 64 + hq] : 0.f;
    float m = pm;
#pragma unroll
    for (int o = 16; o; o >>= 1) m = fmaxf(m, __shfl_xor_sync(0xffffffffu, m, o));
    if ((tid & 31) == 0) redA[tid >> 5] = m;
    __syncthreads();
    float M = fmaxf(fmaxf(redA[0], redA[1]), fmaxf(redA[2], redA[3]));
    float wgt = __expf(pm - M);
    if (tid < 98) swgt[tid] = wgt;
    float l = (tid < 98) ? pl * wgt : 0.f;
#pragma unroll
    for (int o = 16; o; o >>= 1) l += __shfl_xor_sync(0xffffffffu, l, o);
    if ((tid & 31) == 0) redB[tid >> 5] = l;
    __syncthreads();
    float L = redB[0] + redB[1] + redB[2] + redB[3];

    // phase 2: weighted accumulation over chunks, d = tid
    float A = 0.f;
#pragma unroll 7
    for (int c = 0; c < 98; c++)
        A += g_pacc[((base + c) * 64 + hq) * 128 + tid] * swgt[c];
    int t = w * 16 + q;
    g_attn[(size_t)t * 4096 + h * 128 + tid] = A / L;
}

// ----------------------------- launch ---------------------------------------
extern "C" void kernel_launch(void* const* d_in, const int* in_sizes, int n_in,
                              void* d_out, int out_size) {
    const float* hs   = (const float*)d_in[0];
    const float* Wq   = (const float*)d_in[1];
    const float* bq   = (const float*)d_in[2];
    const float* Wk   = (const float*)d_in[3];
    const float* bk   = (const float*)d_in[4];
    const float* Wv   = (const float*)d_in[5];
    const float* bv   = (const float*)d_in[6];
    const float* Wo   = (const float*)d_in[7];
    const float* ssk  = (const float*)d_in[8];
    const float* ssv  = (const float*)d_in[9];
    const float* w0k  = (const float*)d_in[10];
    const float* w0v  = (const float*)d_in[11];
    const float* w1k  = (const float*)d_in[12];
    const float* w1v  = (const float*)d_in[13];
    const float* cosn = (const float*)d_in[14];
    const float* sinn = (const float*)d_in[15];
    float* out = (float*)d_out;

    cudaFuncSetAttribute(attn_kernel,
                         cudaFuncAttributeMaxDynamicSharedMemorySize, 196608);

    qcs_kernel<<<96, 64>>>();

    qkv_gemm_kernel<<<dim3(48, 16), 256>>>(hs, Wq, Wk, Wv);
    reduce_qkv_kernel<<<768, 256>>>(bq, bk, bv);

    rope_q_kernel<<<3072, 128>>>();
    rope_kv_kernel<<<256, 128>>>(cosn, sinn);

    attn_kernel<<<dim3(98, 16), 256, 196608>>>(ssk, ssv, w0k, w0v, w1k, w1v);
    combine_kernel<<<1024, 128>>>();

    o_gemm_kernel<<<dim3(32, 16), 256>>>(Wo);
    reduce_out_kernel<<<512, 256>>>(out);
}

// round 12
// speedup vs baseline: 1.3114x; 1.0021x over previous
#include <cuda_runtime.h>
#include <cuda_bf16.h>
#include <math.h>

typedef unsigned long long ull;

#define SCALE 0.08838834764831843f

// ----------------------------- device scratch -------------------------------
__device__ float  g_qkvp[16 * 32 * 6144];         // k-split partials (QKV)
__device__ float  g_qkv [32 * 6144];              // reduced qkv + bias
__device__ float  g_rqdup[3 * 2 * 32 * 16 * 256]; // roped q, 3 pos-sets, duplicated pairs
__device__ float  g_knew[2 * 8 * 16 * 128];       // roped new keys
__device__ float  g_vnew[2 * 8 * 16 * 128];       // new values
__device__ float  g_pm [16 * 98 * 64];            // split-K partial max
__device__ float  g_pl [16 * 98 * 64];            // split-K partial sum
__device__ float  g_pacc[16 * 98 * 64 * 128];     // split-K partial accum
__device__ float  g_attn[32 * 4096];              // attention out, tokens x (H*D)
__device__ float  g_op [16 * 32 * 4096];          // k-split partials (O proj)
__device__ float2 g_qcs[3 * 2 * 16 * 64];         // q-rope cos/sin table

// ----------------------------- f32x2 helpers --------------------------------
__device__ __forceinline__ ull ffma2(ull a, ull b, ull c) {
    ull d;
    asm("fma.rn.f32x2 %0, %1, %2, %3;" : "=l"(d) : "l"(a), "l"(b), "l"(c));
    return d;
}
__device__ __forceinline__ ull pk2(float x, float y) {
    ull r;
    asm("mov.b64 %0, {%1, %2};" : "=l"(r) : "f"(x), "f"(y));
    return r;
}
__device__ __forceinline__ float2 unpk(ull v) {
    float2 r;
    asm("mov.b64 {%0, %1}, %2;" : "=f"(r.x), "=f"(r.y) : "l"(v));
    return r;
}

// ----------------------------- rope tables ----------------------------------
// loc bases: seg0: 12304 both; seg1: w0->2048, w1->4112; seg2: w0->4112, w1->2048
__global__ void qcs_kernel() {
    int j  = threadIdx.x;          // 0..63
    int b  = blockIdx.x;           // 0..95
    int qi = b & 15;
    int w  = (b >> 4) & 1;
    int seg = b >> 5;
    int base = (seg == 0) ? 12304 : (seg == 1) ? ((w == 0) ? 2048 : 4112)
                                               : ((w == 0) ? 4112 : 2048);
    double inv = exp(-(double)j * 0.14391156831212787);   // ln(10000)/64
    float invf = (float)inv;
    float angf = (float)(base + qi) * invf;               // f32 rounding like reference
    double ang = (double)angf;
    g_qcs[((seg * 2 + w) * 16 + qi) * 64 + j] =
        make_float2((float)cos(ang), (float)sin(ang));
}

__global__ void rope_q_kernel() {
    int d  = threadIdx.x;
    int b  = blockIdx.x;
    int qi = b & 15;
    int h  = (b >> 4) & 31;
    int w  = (b >> 9) & 1;
    int seg = b >> 10;
    int t = w * 16 + qi;
    float qv  = g_qkv[t * 6144 + h * 128 + d];
    float rot = (d < 64) ? -g_qkv[t * 6144 + h * 128 + d + 64]
                         :  g_qkv[t * 6144 + h * 128 + d - 64];
    float2 cs = g_qcs[((seg * 2 + w) * 16 + qi) * 64 + (d & 63)];
    float r = qv * cs.x + rot * cs.y;
    size_t o = ((size_t)(((seg * 2 + w) * 32 + h) * 16 + qi)) * 256 + 2 * d;
    g_rqdup[o] = r;
    g_rqdup[o + 1] = r;
}

__global__ void rope_kv_kernel(const float* __restrict__ cosn,
                               const float* __restrict__ sinn) {
    int d  = threadIdx.x;
    int b  = blockIdx.x;
    int qi = b & 15;
    int kv = (b >> 4) & 7;
    int w  = b >> 7;
    int t = w * 16 + qi;
    float c = cosn[(w * 16 + qi) * 128 + d];
    float s = sinn[(w * 16 + qi) * 128 + d];
    float k   = g_qkv[t * 6144 + 4096 + kv * 128 + d];
    float rot = (d < 64) ? -g_qkv[t * 6144 + 4096 + kv * 128 + d + 64]
                         :  g_qkv[t * 6144 + 4096 + kv * 128 + d - 64];
    int o = ((w * 8 + kv) * 16 + qi) * 128 + d;
    g_knew[o] = k * c + rot * s;
    g_vnew[o] = g_qkv[t * 6144 + 5120 + kv * 128 + d];
}

// ----------------------------- GEMM body ------------------------------------
__device__ __forceinline__ void gemm_body(
    const float* __restrict__ A, const float* __restrict__ W,
    float* __restrict__ Cp, int ldC, int colOff, int K, int KC, int o0) {
    __shared__ float As[64][34];
    __shared__ float Ws[64][132];

    int tid = threadIdx.x;
    int kb  = blockIdx.y * KC;
    int to  = tid & 31;
    int tt  = tid >> 5;

    ull c2[4][2];
#pragma unroll
    for (int i = 0; i < 4; i++) { c2[i][0] = 0ULL; c2[i][1] = 0ULL; }

    for (int kk = 0; kk < KC; kk += 64) {
#pragma unroll
        for (int r = 0; r < 2; r++) {
            int f = tid + r * 256;
            int t = f & 31, kq = f >> 5;
            float4 av = *(const float4*)&A[(size_t)t * K + kb + kk + 4 * kq];
            As[4 * kq + 0][t] = av.x;
            As[4 * kq + 1][t] = av.y;
            As[4 * kq + 2][t] = av.z;
            As[4 * kq + 3][t] = av.w;
        }
#pragma unroll
        for (int r = 0; r < 8; r++) {
            int f = tid + r * 256;
            int o = f & 127, kq = f >> 7;
            float4 wv = *(const float4*)&W[(size_t)(o0 + o) * K + kb + kk + 4 * kq];
            Ws[4 * kq + 0][o] = wv.x;
            Ws[4 * kq + 1][o] = wv.y;
            Ws[4 * kq + 2][o] = wv.z;
            Ws[4 * kq + 3][o] = wv.w;
        }
        __syncthreads();
#pragma unroll 8
        for (int k = 0; k < 64; k++) {
            ull a0 = *(const ull*)&As[k][4 * tt];
            ull a1 = *(const ull*)&As[k][4 * tt + 2];
            float4 wv = *(const float4*)&Ws[k][4 * to];
            ull w0 = pk2(wv.x, wv.x), w1 = pk2(wv.y, wv.y);
            ull w2 = pk2(wv.z, wv.z), w3 = pk2(wv.w, wv.w);
            c2[0][0] = ffma2(w0, a0, c2[0][0]); c2[0][1] = ffma2(w0, a1, c2[0][1]);
            c2[1][0] = ffma2(w1, a0, c2[1][0]); c2[1][1] = ffma2(w1, a1, c2[1][1]);
            c2[2][0] = ffma2(w2, a0, c2[2][0]); c2[2][1] = ffma2(w2, a1, c2[2][1]);
            c2[3][0] = ffma2(w3, a0, c2[3][0]); c2[3][1] = ffma2(w3, a1, c2[3][1]);
        }
        __syncthreads();
    }
    int ks = blockIdx.y;
#pragma unroll
    for (int i = 0; i < 4; i++) {
        int o = o0 + 4 * to + i;
#pragma unroll
        for (int p = 0; p < 2; p++) {
            float2 v = unpk(c2[i][p]);
            int t0 = 4 * tt + 2 * p;
            Cp[(size_t)(ks * 32 + t0) * ldC + colOff + o]     = v.x;
            Cp[(size_t)(ks * 32 + t0 + 1) * ldC + colOff + o] = v.y;
        }
    }
}

__global__ __launch_bounds__(256) void qkv_gemm_kernel(
    const float* __restrict__ A, const float* __restrict__ Wq,
    const float* __restrict__ Wk, const float* __restrict__ Wv) {
    int bx = blockIdx.x;
    const float* W; int o0, colOff;
    if (bx < 32)      { W = Wq; o0 = bx * 128;        colOff = 0;    }
    else if (bx < 40) { W = Wk; o0 = (bx - 32) * 128; colOff = 4096; }
    else              { W = Wv; o0 = (bx - 40) * 128; colOff = 5120; }
    gemm_body(A, W, g_qkvp, 6144, colOff, 4096, 256, o0);
}

__global__ __launch_bounds__(256) void o_gemm_kernel(const float* __restrict__ Wo) {
    gemm_body(g_attn, Wo, g_op, 4096, 0, 4096, 256, blockIdx.x * 128);
}

__global__ void reduce_qkv_kernel(const float* __restrict__ bq,
                                  const float* __restrict__ bk,
                                  const float* __restrict__ bv) {
    int idx = blockIdx.x * 256 + threadIdx.x;   // < 196608
    float s = 0.f;
#pragma unroll
    for (int ks = 0; ks < 16; ks++) s += g_qkvp[(size_t)ks * 196608 + idx];
    int o = idx % 6144;
    float b = (o < 4096) ? bq[o] : (o < 5120 ? bk[o - 4096] : bv[o - 5120]);
    g_qkv[idx] = s + b;
}

__global__ void reduce_out_kernel(float* __restrict__ out) {
    int idx = blockIdx.x * 256 + threadIdx.x;   // < 131072
    float s = 0.f;
#pragma unroll
    for (int ks = 0; ks < 16; ks++) s += g_op[(size_t)ks * 131072 + idx];
    out[idx] = s;
}

// ----------------------------- attention ------------------------------------
// grid (98, 16=w*8+kv), 256 threads, 192KB dynamic smem.
// 8 warps = 4 heads x 2 q-halves; each warp: 8 q x 128 keys (QK) / 128 dims (PV).
// KT2 cell(dp,lp) float4 = (K[2dp][2lp],K[2dp][2lp+1],K[2dp+1][2lp],K[2dp+1][2lp+1])
// V2  cell(lp,dp) float4 = (V[2lp][2dp],V[2lp][2dp+1],V[2lp+1][2dp],V[2lp+1][2dp+1])
__global__ __launch_bounds__(256) void attn_kernel(
    const float* __restrict__ ssk, const float* __restrict__ ssv,
    const float* __restrict__ w0k, const float* __restrict__ w0v,
    const float* __restrict__ w1k, const float* __restrict__ w1v) {
    extern __shared__ float sm[];
    float* KV = sm;
    float* SC = sm + 16384;
    float* RQ = sm + 32768;
    __shared__ float redm[64][4], redl[64][4], mfin[64];

    int tid = threadIdx.x;
    int cid = blockIdx.x, wkv = blockIdx.y;
    int w = wkv >> 3, kv = wkv & 7;

    int seg, nl = 128, ownnew = 0;
    const float *ksrc, *vsrc;
    if (cid < 64) {
        seg = 0;
        size_t off = ((size_t)kv * 8192 + cid * 128) * 128;
        ksrc = ssk + off; vsrc = ssv + off;
    } else if (cid < 81) {
        seg = 1;
        int cc = cid - 64;
        if (cc < 16) {
            size_t off = ((size_t)kv * 2048 + cc * 128) * 128;
            ksrc = w0k + off; vsrc = w0v + off;
        } else {
            nl = 16; ownnew = (w == 0);
            size_t off = (size_t)kv * 16 * 128;
            ksrc = g_knew + off; vsrc = g_vnew + off;
        }
    } else {
        seg = 2;
        int cc = cid - 81;
        if (cc < 16) {
            size_t off = ((size_t)kv * 2048 + cc * 128) * 128;
            ksrc = w1k + off; vsrc = w1v + off;
        } else {
            nl = 16; ownnew = (w == 1);
            size_t off = (size_t)(8 + kv) * 16 * 128;
            ksrc = g_knew + off; vsrc = g_vnew + off;
        }
    }
    int pidx = wkv * 98 + cid;

    // ---- load RQ (dup) for the 4 heads of this kv ----
    {
        const float4* s4 = (const float4*)(g_rqdup +
            (size_t)((seg * 2 + w) * 32 + kv * 4) * 16 * 256);
        float4* d4 = (float4*)RQ;
#pragma unroll
        for (int r = 0; r < 16; r++) d4[tid + r * 256] = s4[tid + r * 256];
    }
    // ---- load K into KT2 cells ----
#pragma unroll
    for (int r = 0; r < 16; r++) {
        int f = tid + r * 256;
        int l = f & 127, dq = f >> 7;        // dq 0..31 (4 dims each)
        float4 v = (l < nl) ? ((const float4*)ksrc)[l * 32 + dq]
                            : make_float4(0.f, 0.f, 0.f, 0.f);
        int lp = l >> 1, h = l & 1;
        int b0 = (2 * dq * 64 + lp) * 4, b1 = ((2 * dq + 1) * 64 + lp) * 4;
        KV[b0 + h]     = v.x;
        KV[b0 + 2 + h] = v.y;
        KV[b1 + h]     = v.z;
        KV[b1 + 2 + h] = v.w;
    }
    __syncthreads();

    int lane = tid & 31, wi = tid >> 5;
    int hh = wi & 3, q0 = (wi >> 2) * 8;      // head, q-half

    // ---- QK: warp=(head,q-half); lane owns keys {2lane,2lane+1,2lane+64,2lane+65}
    {
        ull acc[8][2];
#pragma unroll
        for (int q = 0; q < 8; q++) { acc[q][0] = 0ULL; acc[q][1] = 0ULL; }
        const float* rqh = RQ + (hh * 16 + q0) * 256;
#pragma unroll 2
        for (int dp = 0; dp < 64; dp++) {
            ulonglong2 c0 = *(const ulonglong2*)&KV[(dp * 64 + lane) * 4];
            ulonglong2 c1 = *(const ulonglong2*)&KV[(dp * 64 + lane + 32) * 4];
#pragma unroll
            for (int q = 0; q < 8; q++) {
                ulonglong2 r = *(const ulonglong2*)&rqh[q * 256 + 4 * dp];
                acc[q][0] = ffma2(r.x, c0.x, acc[q][0]);
                acc[q][0] = ffma2(r.y, c0.y, acc[q][0]);
                acc[q][1] = ffma2(r.x, c1.x, acc[q][1]);
                acc[q][1] = ffma2(r.y, c1.y, acc[q][1]);
            }
        }
        int kA = 2 * lane, kB = 2 * lane + 64;
#pragma unroll
        for (int q = 0; q < 8; q++) {
            int qg = q0 + q;
            float2 sA = unpk(acc[q][0]);
            float2 sB = unpk(acc[q][1]);
            float a0 = ((kA     < nl) && (!ownnew || kA     <= qg)) ? sA.x * SCALE : -1e30f;
            float a1 = ((kA + 1 < nl) && (!ownnew || kA + 1 <= qg)) ? sA.y * SCALE : -1e30f;
            float b0 = ((kB     < nl) && (!ownnew || kB     <= qg)) ? sB.x * SCALE : -1e30f;
            float b1 = ((kB + 1 < nl) && (!ownnew || kB + 1 <= qg)) ? sB.y * SCALE : -1e30f;
            *(float4*)&SC[(hh * 16 + qg) * 256 + 4 * lane]       = make_float4(a0, a0, a1, a1);
            *(float4*)&SC[(hh * 16 + qg) * 256 + 128 + 4 * lane] = make_float4(b0, b0, b1, b1);
        }
    }
    __syncthreads();

    // ---- load V into V2 cells (reuse KV region; QK done) ----
#pragma unroll
    for (int r = 0; r < 16; r++) {
        int f = tid + r * 256;
        int l = f & 127, dq = f >> 7;
        float4 v = (l < nl) ? ((const float4*)vsrc)[l * 32 + dq]
                            : make_float4(0.f, 0.f, 0.f, 0.f);
        int lp = l >> 1, h2 = (l & 1) * 2;
        *(float2*)&KV[(lp * 64 + 2 * dq) * 4 + h2]     = make_float2(v.x, v.y);
        *(float2*)&KV[(lp * 64 + 2 * dq + 1) * 4 + h2] = make_float2(v.z, v.w);
    }

    // ---- per-chunk softmax over SC (dup entries) ----
    {
        int hq = tid & 63, part = tid >> 6;   // 4 parts x 32 keys
        float* row = SC + hq * 256;
        float m = -1e30f;
#pragma unroll
        for (int i = 0; i < 32; i++) m = fmaxf(m, row[2 * (part * 32 + i)]);
        redm[hq][part] = m;
        __syncthreads();
        if (tid < 64) {
            mfin[tid] = fmaxf(fmaxf(redm[tid][0], redm[tid][1]),
                              fmaxf(redm[tid][2], redm[tid][3]));
        }
        __syncthreads();
        float mm = mfin[hq];
        float s = 0.f;
#pragma unroll
        for (int i = 0; i < 32; i++) {
            int idx = 2 * (part * 32 + i);
            float p = __expf(row[idx] - mm);
            row[idx] = p; row[idx + 1] = p;
            s += p;
        }
        redl[hq][part] = s;
        __syncthreads();
        if (tid < 64) {
            float L = redl[tid][0] + redl[tid][1] + redl[tid][2] + redl[tid][3];
            g_pm[(size_t)pidx * 64 + tid] = mfin[tid];
            g_pl[(size_t)pidx * 64 + tid] = L;
        }
        __syncthreads();   // probs + V both ready
    }

    // ---- PV: warp=(head,q-half); lane owns dims {2lane,2lane+1,2lane+64,2lane+65}
    {
        ull acc[8][2];
#pragma unroll
        for (int q = 0; q < 8; q++) { acc[q][0] = 0ULL; acc[q][1] = 0ULL; }
        const float* sch = SC + (hh * 16 + q0) * 256;
#pragma unroll 2
        for (int lp = 0; lp < 64; lp++) {
            ulonglong2 v0 = *(const ulonglong2*)&KV[(lp * 64 + lane) * 4];
            ulonglong2 v1 = *(const ulonglong2*)&KV[(lp * 64 + lane + 32) * 4];
#pragma unroll
            for (int q = 0; q < 8; q++) {
                ulonglong2 p = *(const ulonglong2*)&sch[q * 256 + 4 * lp];
                acc[q][0] = ffma2(p.x, v0.x, acc[q][0]);
                acc[q][0] = ffma2(p.y, v0.y, acc[q][0]);
                acc[q][1] = ffma2(p.x, v1.x, acc[q][1]);
                acc[q][1] = ffma2(p.y, v1.y, acc[q][1]);
            }
        }
#pragma unroll
        for (int q = 0; q < 8; q++) {
            int qg = q0 + q;
            float2 a = unpk(acc[q][0]);
            float2 b = unpk(acc[q][1]);
            size_t base = ((size_t)pidx * 64 + hh * 16 + qg) * 128;
            *(float2*)&g_pacc[base + 2 * lane]      = a;
            *(float2*)&g_pacc[base + 2 * lane + 64] = b;
        }
    }
}

// split-K combine: grid 1024 = (w,h,q), 128 threads
__global__ __launch_bounds__(128) void combine_kernel() {
    __shared__ float swgt[98];
    __shared__ float redA[4], redB[4];
    int b = blockIdx.x;
    int q = b & 15, h = (b >> 4) & 31, w = b >> 9;
    int kv = h >> 2;
    int hq = (h & 3) * 16 + q;
    size_t base = (size_t)(w * 8 + kv) * 98;
    int tid = threadIdx.x;

    // phase 1: chunk-parallel M, L, weights
    float pm = (tid < 98) ? g_pm[(base + tid) * 64 + hq] : -3e38f;
    float pl = (tid < 98) ? g_pl[(base + tid) * 64 + hq] : 0.f;
    float m = pm;
#pragma unroll
    for (int o = 16; o; o >>= 1) m = fmaxf(m, __shfl_xor_sync(0xffffffffu, m, o));
    if ((tid & 31) == 0) redA[tid >> 5] = m;
    __syncthreads();
    float M = fmaxf(fmaxf(redA[0], redA[1]), fmaxf(redA[2], redA[3]));
    float wgt = __expf(pm - M);
    if (tid < 98) swgt[tid] = wgt;
    float l = (tid < 98) ? pl * wgt : 0.f;
#pragma unroll
    for (int o = 16; o; o >>= 1) l += __shfl_xor_sync(0xffffffffu, l, o);
    if ((tid & 31) == 0) redB[tid >> 5] = l;
    __syncthreads();
    float L = redB[0] + redB[1] + redB[2] + redB[3];

    // phase 2: weighted accumulation over chunks, d = tid
    float A = 0.f;
#pragma unroll 7
    for (int c = 0; c < 98; c++)
        A += g_pacc[((base + c) * 64 + hq) * 128 + tid] * swgt[c];
    int t = w * 16 + q;
    g_attn[(size_t)t * 4096 + h * 128 + tid] = A / L;
}

// ----------------------------- launch ---------------------------------------
extern "C" void kernel_launch(void* const* d_in, const int* in_sizes, int n_in,
                              void* d_out, int out_size) {
    const float* hs   = (const float*)d_in[0];
    const float* Wq   = (const float*)d_in[1];
    const float* bq   = (const float*)d_in[2];
    const float* Wk   = (const float*)d_in[3];
    const float* bk   = (const float*)d_in[4];
    const float* Wv   = (const float*)d_in[5];
    const float* bv   = (const float*)d_in[6];
    const float* Wo   = (const float*)d_in[7];
    const float* ssk  = (const float*)d_in[8];
    const float* ssv  = (const float*)d_in[9];
    const float* w0k  = (const float*)d_in[10];
    const float* w0v  = (const float*)d_in[11];
    const float* w1k  = (const float*)d_in[12];
    const float* w1v  = (const float*)d_in[13];
    const float* cosn = (const float*)d_in[14];
    const float* sinn = (const float*)d_in[15];
    float* out = (float*)d_out;

    cudaFuncSetAttribute(attn_kernel,
                         cudaFuncAttributeMaxDynamicSharedMemorySize, 196608);

    qcs_kernel<<<96, 64>>>();

    qkv_gemm_kernel<<<dim3(48, 16), 256>>>(hs, Wq, Wk, Wv);
    reduce_qkv_kernel<<<768, 256>>>(bq, bk, bv);

    rope_q_kernel<<<3072, 128>>>();
    rope_kv_kernel<<<256, 128>>>(cosn, sinn);

    attn_kernel<<<dim3(98, 16), 256, 196608>>>(ssk, ssv, w0k, w0v, w1k, w1v);
    combine_kernel<<<1024, 128>>>();

    o_gemm_kernel<<<dim3(32, 16), 256>>>(Wo);
    reduce_out_kernel<<<512, 256>>>(out);
}

// round 13
// speedup vs baseline: 1.4889x; 1.1353x over previous
#include <cuda_runtime.h>
#include <cuda_bf16.h>
#include <math.h>

typedef unsigned long long ull;

#define SCALE 0.08838834764831843f
#define SCS 260   // SC row stride (floats): 1040B -> 4-way instead of 32-way conflicts

// ----------------------------- device scratch -------------------------------
__device__ float  g_qkvp[16 * 32 * 6144];         // k-split partials (QKV)
__device__ float  g_qkv [32 * 6144];              // reduced qkv + bias
__device__ float  g_rqdup[3 * 2 * 32 * 16 * 256]; // roped q, 3 pos-sets, duplicated pairs
__device__ float  g_knew[2 * 8 * 16 * 128];       // roped new keys
__device__ float  g_vnew[2 * 8 * 16 * 128];       // new values
__device__ float  g_pm [16 * 98 * 64];            // split-K partial max
__device__ float  g_pl [16 * 98 * 64];            // split-K partial sum
__device__ float  g_pacc[16 * 98 * 64 * 128];     // split-K partial accum
__device__ float  g_attn[32 * 4096];              // attention out, tokens x (H*D)
__device__ float  g_op [16 * 32 * 4096];          // k-split partials (O proj)

// ----------------------------- f32x2 helpers --------------------------------
__device__ __forceinline__ ull ffma2(ull a, ull b, ull c) {
    ull d;
    asm("fma.rn.f32x2 %0, %1, %2, %3;" : "=l"(d) : "l"(a), "l"(b), "l"(c));
    return d;
}
__device__ __forceinline__ ull pk2(float x, float y) {
    ull r;
    asm("mov.b64 %0, {%1, %2};" : "=l"(r) : "f"(x), "f"(y));
    return r;
}
__device__ __forceinline__ float2 unpk(ull v) {
    float2 r;
    asm("mov.b64 {%0, %1}, %2;" : "=f"(r.x), "=f"(r.y) : "l"(v));
    return r;
}

// ----------------------------- fused rope -----------------------------------
// blocks [0,3072): q-rope (inline cos/sin, double path); [3072,3328): kv-rope
// loc bases: seg0: 12304 both; seg1: w0->2048, w1->4112; seg2: w0->4112, w1->2048
__global__ void rope_all_kernel(const float* __restrict__ cosn,
                                const float* __restrict__ sinn) {
    int d = threadIdx.x;
    int b = blockIdx.x;
    if (b < 3072) {
        int qi = b & 15;
        int h  = (b >> 4) & 31;
        int w  = (b >> 9) & 1;
        int seg = b >> 10;
        int base = (seg == 0) ? 12304 : (seg == 1) ? ((w == 0) ? 2048 : 4112)
                                                   : ((w == 0) ? 4112 : 2048);
        int j = d & 63;
        double inv = exp(-(double)j * 0.14391156831212787);   // ln(10000)/64
        float invf = (float)inv;
        float angf = (float)(base + qi) * invf;               // f32 rounding like ref
        double ang = (double)angf;
        float c = (float)cos(ang), s = (float)sin(ang);
        int t = w * 16 + qi;
        float qv  = g_qkv[t * 6144 + h * 128 + d];
        float rot = (d < 64) ? -g_qkv[t * 6144 + h * 128 + d + 64]
                             :  g_qkv[t * 6144 + h * 128 + d - 64];
        float r = qv * c + rot * s;
        size_t o = ((size_t)(((seg * 2 + w) * 32 + h) * 16 + qi)) * 256 + 2 * d;
        g_rqdup[o] = r;
        g_rqdup[o + 1] = r;
    } else {
        int bb = b - 3072;
        int qi = bb & 15;
        int kv = (bb >> 4) & 7;
        int w  = bb >> 7;
        int t = w * 16 + qi;
        float c = cosn[(w * 16 + qi) * 128 + d];
        float s = sinn[(w * 16 + qi) * 128 + d];
        float k   = g_qkv[t * 6144 + 4096 + kv * 128 + d];
        float rot = (d < 64) ? -g_qkv[t * 6144 + 4096 + kv * 128 + d + 64]
                             :  g_qkv[t * 6144 + 4096 + kv * 128 + d - 64];
        int o = ((w * 8 + kv) * 16 + qi) * 128 + d;
        g_knew[o] = k * c + rot * s;
        g_vnew[o] = g_qkv[t * 6144 + 5120 + kv * 128 + d];
    }
}

// ----------------------------- GEMM body ------------------------------------
__device__ __forceinline__ void gemm_body(
    const float* __restrict__ A, const float* __restrict__ W,
    float* __restrict__ Cp, int ldC, int colOff, int K, int KC, int o0) {
    __shared__ float As[64][34];
    __shared__ float Ws[64][132];

    int tid = threadIdx.x;
    int kb  = blockIdx.y * KC;
    int to  = tid & 31;
    int tt  = tid >> 5;

    ull c2[4][2];
#pragma unroll
    for (int i = 0; i < 4; i++) { c2[i][0] = 0ULL; c2[i][1] = 0ULL; }

    for (int kk = 0; kk < KC; kk += 64) {
#pragma unroll
        for (int r = 0; r < 2; r++) {
            int f = tid + r * 256;
            int t = f & 31, kq = f >> 5;
            float4 av = *(const float4*)&A[(size_t)t * K + kb + kk + 4 * kq];
            As[4 * kq + 0][t] = av.x;
            As[4 * kq + 1][t] = av.y;
            As[4 * kq + 2][t] = av.z;
            As[4 * kq + 3][t] = av.w;
        }
#pragma unroll
        for (int r = 0; r < 8; r++) {
            int f = tid + r * 256;
            int o = f & 127, kq = f >> 7;
            float4 wv = *(const float4*)&W[(size_t)(o0 + o) * K + kb + kk + 4 * kq];
            Ws[4 * kq + 0][o] = wv.x;
            Ws[4 * kq + 1][o] = wv.y;
            Ws[4 * kq + 2][o] = wv.z;
            Ws[4 * kq + 3][o] = wv.w;
        }
        __syncthreads();
#pragma unroll 8
        for (int k = 0; k < 64; k++) {
            ull a0 = *(const ull*)&As[k][4 * tt];
            ull a1 = *(const ull*)&As[k][4 * tt + 2];
            float4 wv = *(const float4*)&Ws[k][4 * to];
            ull w0 = pk2(wv.x, wv.x), w1 = pk2(wv.y, wv.y);
            ull w2 = pk2(wv.z, wv.z), w3 = pk2(wv.w, wv.w);
            c2[0][0] = ffma2(w0, a0, c2[0][0]); c2[0][1] = ffma2(w0, a1, c2[0][1]);
            c2[1][0] = ffma2(w1, a0, c2[1][0]); c2[1][1] = ffma2(w1, a1, c2[1][1]);
            c2[2][0] = ffma2(w2, a0, c2[2][0]); c2[2][1] = ffma2(w2, a1, c2[2][1]);
            c2[3][0] = ffma2(w3, a0, c2[3][0]); c2[3][1] = ffma2(w3, a1, c2[3][1]);
        }
        __syncthreads();
    }
    int ks = blockIdx.y;
#pragma unroll
    for (int i = 0; i < 4; i++) {
        int o = o0 + 4 * to + i;
#pragma unroll
        for (int p = 0; p < 2; p++) {
            float2 v = unpk(c2[i][p]);
            int t0 = 4 * tt + 2 * p;
            Cp[(size_t)(ks * 32 + t0) * ldC + colOff + o]     = v.x;
            Cp[(size_t)(ks * 32 + t0 + 1) * ldC + colOff + o] = v.y;
        }
    }
}

__global__ __launch_bounds__(256) void qkv_gemm_kernel(
    const float* __restrict__ A, const float* __restrict__ Wq,
    const float* __restrict__ Wk, const float* __restrict__ Wv) {
    int bx = blockIdx.x;
    const float* W; int o0, colOff;
    if (bx < 32)      { W = Wq; o0 = bx * 128;        colOff = 0;    }
    else if (bx < 40) { W = Wk; o0 = (bx - 32) * 128; colOff = 4096; }
    else              { W = Wv; o0 = (bx - 40) * 128; colOff = 5120; }
    gemm_body(A, W, g_qkvp, 6144, colOff, 4096, 256, o0);
}

__global__ __launch_bounds__(256) void o_gemm_kernel(const float* __restrict__ Wo) {
    gemm_body(g_attn, Wo, g_op, 4096, 0, 4096, 256, blockIdx.x * 128);
}

__global__ void reduce_qkv_kernel(const float* __restrict__ bq,
                                  const float* __restrict__ bk,
                                  const float* __restrict__ bv) {
    int idx = blockIdx.x * 256 + threadIdx.x;   // < 196608
    float s = 0.f;
#pragma unroll
    for (int ks = 0; ks < 16; ks++) s += g_qkvp[(size_t)ks * 196608 + idx];
    int o = idx % 6144;
    float b = (o < 4096) ? bq[o] : (o < 5120 ? bk[o - 4096] : bv[o - 5120]);
    g_qkv[idx] = s + b;
}

__global__ void reduce_out_kernel(float* __restrict__ out) {
    int idx = blockIdx.x * 256 + threadIdx.x;   // < 131072
    float s = 0.f;
#pragma unroll
    for (int ks = 0; ks < 16; ks++) s += g_op[(size_t)ks * 131072 + idx];
    out[idx] = s;
}

// ----------------------------- attention ------------------------------------
// grid (98, 16=w*8+kv), 256 threads.
// smem: KV cells [0,16640); SC dup rows stride SCS [16640,33280); RQ dup [33280,49664)
// KT2 cell(dp,lp) @ dp*64+lp ; V2 cell(lp,dp) @ lp*65+dp  (65 => conflict-light stores)
__global__ __launch_bounds__(256) void attn_kernel(
    const float* __restrict__ ssk, const float* __restrict__ ssv,
    const float* __restrict__ w0k, const float* __restrict__ w0v,
    const float* __restrict__ w1k, const float* __restrict__ w1v) {
    extern __shared__ float sm[];
    float* KV = sm;
    float* SC = sm + 16640;
    float* RQ = sm + 33280;
    __shared__ float redm[64][4], redl[64][4], mfin[64];

    int tid = threadIdx.x;
    int cid = blockIdx.x, wkv = blockIdx.y;
    int w = wkv >> 3, kv = wkv & 7;

    int seg, nl = 128, ownnew = 0;
    const float *ksrc, *vsrc;
    if (cid < 64) {
        seg = 0;
        size_t off = ((size_t)kv * 8192 + cid * 128) * 128;
        ksrc = ssk + off; vsrc = ssv + off;
    } else if (cid < 81) {
        seg = 1;
        int cc = cid - 64;
        if (cc < 16) {
            size_t off = ((size_t)kv * 2048 + cc * 128) * 128;
            ksrc = w0k + off; vsrc = w0v + off;
        } else {
            nl = 16; ownnew = (w == 0);
            size_t off = (size_t)kv * 16 * 128;
            ksrc = g_knew + off; vsrc = g_vnew + off;
        }
    } else {
        seg = 2;
        int cc = cid - 81;
        if (cc < 16) {
            size_t off = ((size_t)kv * 2048 + cc * 128) * 128;
            ksrc = w1k + off; vsrc = w1v + off;
        } else {
            nl = 16; ownnew = (w == 1);
            size_t off = (size_t)(8 + kv) * 16 * 128;
            ksrc = g_knew + off; vsrc = g_vnew + off;
        }
    }
    int pidx = wkv * 98 + cid;

    // ---- load RQ (dup) for the 4 heads of this kv ----
    {
        const float4* s4 = (const float4*)(g_rqdup +
            (size_t)((seg * 2 + w) * 32 + kv * 4) * 16 * 256);
        float4* d4 = (float4*)RQ;
#pragma unroll
        for (int r = 0; r < 16; r++) d4[tid + r * 256] = s4[tid + r * 256];
    }
    // ---- load K into KT2 cells ----
#pragma unroll
    for (int r = 0; r < 16; r++) {
        int f = tid + r * 256;
        int l = f & 127, dq = f >> 7;        // dq 0..31 (4 dims each)
        float4 v = (l < nl) ? ((const float4*)ksrc)[l * 32 + dq]
                            : make_float4(0.f, 0.f, 0.f, 0.f);
        int lp = l >> 1, h = l & 1;
        int b0 = (2 * dq * 64 + lp) * 4, b1 = ((2 * dq + 1) * 64 + lp) * 4;
        KV[b0 + h]     = v.x;
        KV[b0 + 2 + h] = v.y;
        KV[b1 + h]     = v.z;
        KV[b1 + 2 + h] = v.w;
    }
    __syncthreads();

    int lane = tid & 31, wi = tid >> 5;
    int hh = wi & 3, q0 = (wi >> 2) * 8;      // head, q-half

    // ---- QK: warp=(head,q-half); lane owns keys {2lane,2lane+1,2lane+64,2lane+65}
    {
        ull acc[8][2];
#pragma unroll
        for (int q = 0; q < 8; q++) { acc[q][0] = 0ULL; acc[q][1] = 0ULL; }
        const float* rqh = RQ + (hh * 16 + q0) * 256;
#pragma unroll 2
        for (int dp = 0; dp < 64; dp++) {
            ulonglong2 c0 = *(const ulonglong2*)&KV[(dp * 64 + lane) * 4];
            ulonglong2 c1 = *(const ulonglong2*)&KV[(dp * 64 + lane + 32) * 4];
#pragma unroll
            for (int q = 0; q < 8; q++) {
                ulonglong2 r = *(const ulonglong2*)&rqh[q * 256 + 4 * dp];
                acc[q][0] = ffma2(r.x, c0.x, acc[q][0]);
                acc[q][0] = ffma2(r.y, c0.y, acc[q][0]);
                acc[q][1] = ffma2(r.x, c1.x, acc[q][1]);
                acc[q][1] = ffma2(r.y, c1.y, acc[q][1]);
            }
        }
        int kA = 2 * lane, kB = 2 * lane + 64;
#pragma unroll
        for (int q = 0; q < 8; q++) {
            int qg = q0 + q;
            float2 sA = unpk(acc[q][0]);
            float2 sB = unpk(acc[q][1]);
            float a0 = ((kA     < nl) && (!ownnew || kA     <= qg)) ? sA.x * SCALE : -1e30f;
            float a1 = ((kA + 1 < nl) && (!ownnew || kA + 1 <= qg)) ? sA.y * SCALE : -1e30f;
            float b0 = ((kB     < nl) && (!ownnew || kB     <= qg)) ? sB.x * SCALE : -1e30f;
            float b1 = ((kB + 1 < nl) && (!ownnew || kB + 1 <= qg)) ? sB.y * SCALE : -1e30f;
            *(float4*)&SC[(hh * 16 + qg) * SCS + 4 * lane]       = make_float4(a0, a0, a1, a1);
            *(float4*)&SC[(hh * 16 + qg) * SCS + 128 + 4 * lane] = make_float4(b0, b0, b1, b1);
        }
    }
    __syncthreads();

    // ---- load V into V2 cells (reuse KV region; QK done) ----
#pragma unroll
    for (int r = 0; r < 16; r++) {
        int f = tid + r * 256;
        int l = f & 127, dq = f >> 7;
        float4 v = (l < nl) ? ((const float4*)vsrc)[l * 32 + dq]
                            : make_float4(0.f, 0.f, 0.f, 0.f);
        int lp = l >> 1, h2 = (l & 1) * 2;
        *(float2*)&KV[(lp * 65 + 2 * dq) * 4 + h2]     = make_float2(v.x, v.y);
        *(float2*)&KV[(lp * 65 + 2 * dq + 1) * 4 + h2] = make_float2(v.z, v.w);
    }

    // ---- per-chunk softmax over SC (dup entries; stride SCS => 4-way max) ----
    {
        int hq = tid & 63, part = tid >> 6;   // 4 parts x 32 keys
        float* row = SC + hq * SCS;
        float m = -1e30f;
#pragma unroll
        for (int i = 0; i < 32; i++) m = fmaxf(m, row[2 * (part * 32 + i)]);
        redm[hq][part] = m;
        __syncthreads();
        if (tid < 64) {
            mfin[tid] = fmaxf(fmaxf(redm[tid][0], redm[tid][1]),
                              fmaxf(redm[tid][2], redm[tid][3]));
        }
        __syncthreads();
        float mm = mfin[hq];
        float s = 0.f;
#pragma unroll
        for (int i = 0; i < 32; i++) {
            int idx = 2 * (part * 32 + i);
            float p = __expf(row[idx] - mm);
            row[idx] = p; row[idx + 1] = p;
            s += p;
        }
        redl[hq][part] = s;
        __syncthreads();
        if (tid < 64) {
            float L = redl[tid][0] + redl[tid][1] + redl[tid][2] + redl[tid][3];
            g_pm[(size_t)pidx * 64 + tid] = mfin[tid];
            g_pl[(size_t)pidx * 64 + tid] = L;
        }
        __syncthreads();   // probs + V both ready
    }

    // ---- PV: warp=(head,q-half); lane owns dims {2lane,2lane+1,2lane+64,2lane+65}
    {
        ull acc[8][2];
#pragma unroll
        for (int q = 0; q < 8; q++) { acc[q][0] = 0ULL; acc[q][1] = 0ULL; }
        const float* sch = SC + (hh * 16 + q0) * SCS;
#pragma unroll 2
        for (int lp = 0; lp < 64; lp++) {
            ulonglong2 v0 = *(const ulonglong2*)&KV[(lp * 65 + lane) * 4];
            ulonglong2 v1 = *(const ulonglong2*)&KV[(lp * 65 + lane + 32) * 4];
#pragma unroll
            for (int q = 0; q < 8; q++) {
                ulonglong2 p = *(const ulonglong2*)&sch[q * SCS + 4 * lp];
                acc[q][0] = ffma2(p.x, v0.x, acc[q][0]);
                acc[q][0] = ffma2(p.y, v0.y, acc[q][0]);
                acc[q][1] = ffma2(p.x, v1.x, acc[q][1]);
                acc[q][1] = ffma2(p.y, v1.y, acc[q][1]);
            }
        }
#pragma unroll
        for (int q = 0; q < 8; q++) {
            int qg = q0 + q;
            float2 a = unpk(acc[q][0]);
            float2 b = unpk(acc[q][1]);
            size_t base = ((size_t)pidx * 64 + hh * 16 + qg) * 128;
            *(float2*)&g_pacc[base + 2 * lane]      = a;
            *(float2*)&g_pacc[base + 2 * lane + 64] = b;
        }
    }
}

// split-K combine: grid 1024 = (w,h,q), 128 threads
__global__ __launch_bounds__(128) void combine_kernel() {
    __shared__ float swgt[98];
    __shared__ float redA[4], redB[4];
    int b = blockIdx.x;
    int q = b & 15, h = (b >> 4) & 31, w = b >> 9;
    int kv = h >> 2;
    int hq = (h & 3) * 16 + q;
    size_t base = (size_t)(w * 8 + kv) * 98;
    int tid = threadIdx.x;

    float pm = (tid < 98) ? g_pm[(base + tid) * 64 + hq] : -3e38f;
    float pl = (tid < 98) ? g_pl[(base + tid) * 64 + hq] : 0.f;
    float m = pm;
#pragma unroll
    for (int o = 16; o; o >>= 1) m = fmaxf(m, __shfl_xor_sync(0xffffffffu, m, o));
    if ((tid & 31) == 0) redA[tid >> 5] = m;
    __syncthreads();
    float M = fmaxf(fmaxf(redA[0], redA[1]), fmaxf(redA[2], redA[3]));
    float wgt = __expf(pm - M);
    if (tid < 98) swgt[tid] = wgt;
    float l = (tid < 98) ? pl * wgt : 0.f;
#pragma unroll
    for (int o = 16; o; o >>= 1) l += __shfl_xor_sync(0xffffffffu, l, o);
    if ((tid & 31) == 0) redB[tid >> 5] = l;
    __syncthreads();
    float L = redB[0] + redB[1] + redB[2] + redB[3];

    float A = 0.f;
#pragma unroll 7
    for (int c = 0; c < 98; c++)
        A += g_pacc[((base + c) * 64 + hq) * 128 + tid] * swgt[c];
    int t = w * 16 + q;
    g_attn[(size_t)t * 4096 + h * 128 + tid] = A / L;
}

// ----------------------------- launch ---------------------------------------
extern "C" void kernel_launch(void* const* d_in, const int* in_sizes, int n_in,
                              void* d_out, int out_size) {
    const float* hs   = (const float*)d_in[0];
    const float* Wq   = (const float*)d_in[1];
    const float* bq   = (const float*)d_in[2];
    const float* Wk   = (const float*)d_in[3];
    const float* bk   = (const float*)d_in[4];
    const float* Wv   = (const float*)d_in[5];
    const float* bv   = (const float*)d_in[6];
    const float* Wo   = (const float*)d_in[7];
    const float* ssk  = (const float*)d_in[8];
    const float* ssv  = (const float*)d_in[9];
    const float* w0k  = (const float*)d_in[10];
    const float* w0v  = (const float*)d_in[11];
    const float* w1k  = (const float*)d_in[12];
    const float* w1v  = (const float*)d_in[13];
    const float* cosn = (const float*)d_in[14];
    const float* sinn = (const float*)d_in[15];
    float* out = (float*)d_out;

    cudaFuncSetAttribute(attn_kernel,
                         cudaFuncAttributeMaxDynamicSharedMemorySize, 198656);

    qkv_gemm_kernel<<<dim3(48, 16), 256>>>(hs, Wq, Wk, Wv);
    reduce_qkv_kernel<<<768, 256>>>(bq, bk, bv);
    rope_all_kernel<<<3328, 128>>>(cosn, sinn);

    attn_kernel<<<dim3(98, 16), 256, 198656>>>(ssk, ssv, w0k, w0v, w1k, w1v);
    combine_kernel<<<1024, 128>>>();

    o_gemm_kernel<<<dim3(32, 16), 256>>>(Wo);
    reduce_out_kernel<<<512, 256>>>(out);
}

// round 14
// speedup vs baseline: 1.7039x; 1.1444x over previous
#include <cuda_runtime.h>
#include <cuda_bf16.h>
#include <math.h>

typedef unsigned long long ull;

#define SCALE 0.08838834764831843f

// ----------------------------- device scratch -------------------------------
__device__ float  g_qkvp[16 * 32 * 6144];         // k-split partials (QKV)
__device__ float  g_qkv [32 * 6144];              // reduced qkv + bias
__device__ float  g_rqt [48 * 128 * 64];          // roped q, transposed [set][d][hq]
__device__ float  g_knew[2 * 8 * 16 * 128];       // roped new keys
__device__ float  g_vnew[2 * 8 * 16 * 128];       // new values
__device__ float  g_pm [16 * 98 * 64];            // split-K partial max
__device__ float  g_pl [16 * 98 * 64];            // split-K partial sum
__device__ float  g_pacc[16 * 98 * 64 * 128];     // split-K partial accum
__device__ float  g_attn[32 * 4096];              // attention out, tokens x (H*D)
__device__ float  g_op [16 * 32 * 4096];          // k-split partials (O proj)

// ----------------------------- f32x2 helpers --------------------------------
__device__ __forceinline__ ull ffma2(ull a, ull b, ull c) {
    ull d;
    asm("fma.rn.f32x2 %0, %1, %2, %3;" : "=l"(d) : "l"(a), "l"(b), "l"(c));
    return d;
}
__device__ __forceinline__ ull pk2(float x, float y) {
    ull r;
    asm("mov.b64 %0, {%1, %2};" : "=l"(r) : "f"(x), "f"(y));
    return r;
}
__device__ __forceinline__ float2 unpk(ull v) {
    float2 r;
    asm("mov.b64 {%0, %1}, %2;" : "=f"(r.x), "=f"(r.y) : "l"(v));
    return r;
}

// ----------------------------- fused rope -----------------------------------
// blocks [0,3072): q-rope; [3072,3328): kv-rope
// loc bases: seg0: 12304 both; seg1: w0->2048, w1->4112; seg2: w0->4112, w1->2048
__global__ void rope_all_kernel(const float* __restrict__ cosn,
                                const float* __restrict__ sinn) {
    int d = threadIdx.x;
    int b = blockIdx.x;
    if (b < 3072) {
        int qi = b & 15;
        int h  = (b >> 4) & 31;
        int w  = (b >> 9) & 1;
        int seg = b >> 10;
        int base = (seg == 0) ? 12304 : (seg == 1) ? ((w == 0) ? 2048 : 4112)
                                                   : ((w == 0) ? 4112 : 2048);
        int j = d & 63;
        double inv = exp(-(double)j * 0.14391156831212787);   // ln(10000)/64
        float invf = (float)inv;
        float angf = (float)(base + qi) * invf;               // f32 rounding like ref
        double ang = (double)angf;
        float c = (float)cos(ang), s = (float)sin(ang);
        int t = w * 16 + qi;
        float qv  = g_qkv[t * 6144 + h * 128 + d];
        float rot = (d < 64) ? -g_qkv[t * 6144 + h * 128 + d + 64]
                             :  g_qkv[t * 6144 + h * 128 + d - 64];
        float r = qv * c + rot * s;
        // transposed: [ (seg*2+w)*8 + kv ][ d ][ hq = hh*16+qi ]
        size_t o = ((size_t)((seg * 2 + w) * 8 + (h >> 2))) * 8192
                 + (size_t)d * 64 + ((h & 3) * 16 + qi);
        g_rqt[o] = r;
    } else {
        int bb = b - 3072;
        int qi = bb & 15;
        int kv = (bb >> 4) & 7;
        int w  = bb >> 7;
        int t = w * 16 + qi;
        float c = cosn[(w * 16 + qi) * 128 + d];
        float s = sinn[(w * 16 + qi) * 128 + d];
        float k   = g_qkv[t * 6144 + 4096 + kv * 128 + d];
        float rot = (d < 64) ? -g_qkv[t * 6144 + 4096 + kv * 128 + d + 64]
                             :  g_qkv[t * 6144 + 4096 + kv * 128 + d - 64];
        int o = ((w * 8 + kv) * 16 + qi) * 128 + d;
        g_knew[o] = k * c + rot * s;
        g_vnew[o] = g_qkv[t * 6144 + 5120 + kv * 128 + d];
    }
}

// ----------------------------- GEMM body ------------------------------------
__device__ __forceinline__ void gemm_body(
    const float* __restrict__ A, const float* __restrict__ W,
    float* __restrict__ Cp, int ldC, int colOff, int K, int KC, int o0) {
    __shared__ float As[64][34];
    __shared__ float Ws[64][132];

    int tid = threadIdx.x;
    int kb  = blockIdx.y * KC;
    int to  = tid & 31;
    int tt  = tid >> 5;

    ull c2[4][2];
#pragma unroll
    for (int i = 0; i < 4; i++) { c2[i][0] = 0ULL; c2[i][1] = 0ULL; }

    for (int kk = 0; kk < KC; kk += 64) {
#pragma unroll
        for (int r = 0; r < 2; r++) {
            int f = tid + r * 256;
            int t = f & 31, kq = f >> 5;
            float4 av = *(const float4*)&A[(size_t)t * K + kb + kk + 4 * kq];
            As[4 * kq + 0][t] = av.x;
            As[4 * kq + 1][t] = av.y;
            As[4 * kq + 2][t] = av.z;
            As[4 * kq + 3][t] = av.w;
        }
#pragma unroll
        for (int r = 0; r < 8; r++) {
            int f = tid + r * 256;
            int o = f & 127, kq = f >> 7;
            float4 wv = *(const float4*)&W[(size_t)(o0 + o) * K + kb + kk + 4 * kq];
            Ws[4 * kq + 0][o] = wv.x;
            Ws[4 * kq + 1][o] = wv.y;
            Ws[4 * kq + 2][o] = wv.z;
            Ws[4 * kq + 3][o] = wv.w;
        }
        __syncthreads();
#pragma unroll 8
        for (int k = 0; k < 64; k++) {
            ull a0 = *(const ull*)&As[k][4 * tt];
            ull a1 = *(const ull*)&As[k][4 * tt + 2];
            float4 wv = *(const float4*)&Ws[k][4 * to];
            ull w0 = pk2(wv.x, wv.x), w1 = pk2(wv.y, wv.y);
            ull w2 = pk2(wv.z, wv.z), w3 = pk2(wv.w, wv.w);
            c2[0][0] = ffma2(w0, a0, c2[0][0]); c2[0][1] = ffma2(w0, a1, c2[0][1]);
            c2[1][0] = ffma2(w1, a0, c2[1][0]); c2[1][1] = ffma2(w1, a1, c2[1][1]);
            c2[2][0] = ffma2(w2, a0, c2[2][0]); c2[2][1] = ffma2(w2, a1, c2[2][1]);
            c2[3][0] = ffma2(w3, a0, c2[3][0]); c2[3][1] = ffma2(w3, a1, c2[3][1]);
        }
        __syncthreads();
    }
    int ks = blockIdx.y;
#pragma unroll
    for (int i = 0; i < 4; i++) {
        int o = o0 + 4 * to + i;
#pragma unroll
        for (int p = 0; p < 2; p++) {
            float2 v = unpk(c2[i][p]);
            int t0 = 4 * tt + 2 * p;
            Cp[(size_t)(ks * 32 + t0) * ldC + colOff + o]     = v.x;
            Cp[(size_t)(ks * 32 + t0 + 1) * ldC + colOff + o] = v.y;
        }
    }
}

__global__ __launch_bounds__(256) void qkv_gemm_kernel(
    const float* __restrict__ A, const float* __restrict__ Wq,
    const float* __restrict__ Wk, const float* __restrict__ Wv) {
    int bx = blockIdx.x;
    const float* W; int o0, colOff;
    if (bx < 32)      { W = Wq; o0 = bx * 128;        colOff = 0;    }
    else if (bx < 40) { W = Wk; o0 = (bx - 32) * 128; colOff = 4096; }
    else              { W = Wv; o0 = (bx - 40) * 128; colOff = 5120; }
    gemm_body(A, W, g_qkvp, 6144, colOff, 4096, 256, o0);
}

__global__ __launch_bounds__(256) void o_gemm_kernel(const float* __restrict__ Wo) {
    gemm_body(g_attn, Wo, g_op, 4096, 0, 4096, 256, blockIdx.x * 128);
}

__global__ void reduce_qkv_kernel(const float* __restrict__ bq,
                                  const float* __restrict__ bk,
                                  const float* __restrict__ bv) {
    int idx = blockIdx.x * 256 + threadIdx.x;   // < 196608
    float s = 0.f;
#pragma unroll
    for (int ks = 0; ks < 16; ks++) s += g_qkvp[(size_t)ks * 196608 + idx];
    int o = idx % 6144;
    float b = (o < 4096) ? bq[o] : (o < 5120 ? bk[o - 4096] : bv[o - 5120]);
    g_qkv[idx] = s + b;
}

__global__ void reduce_out_kernel(float* __restrict__ out) {
    int idx = blockIdx.x * 256 + threadIdx.x;   // < 131072
    float s = 0.f;
#pragma unroll
    for (int ks = 0; ks < 16; ks++) s += g_op[(size_t)ks * 131072 + idx];
    out[idx] = s;
}

// ----------------------------- attention ------------------------------------
// grid (98, 16=w*8+kv), 256 threads.
// smem: KT [0,16896) rows d stride 132 (later V rows l stride 132)
//       SCt [16896,25600) rows key stride 68 (score[key][hq])
//       RQt [25600,34304) rows d stride 68 (rq[d][hq], non-dup)
// 8 warps = 4 heads x 2 q-halves. Lane owns 4 q-pairs x 4 keys/dims.
__global__ __launch_bounds__(256) void attn_kernel(
    const float* __restrict__ ssk, const float* __restrict__ ssv,
    const float* __restrict__ w0k, const float* __restrict__ w0v,
    const float* __restrict__ w1k, const float* __restrict__ w1v) {
    extern __shared__ float sm[];
    float* KT  = sm;
    float* SCt = sm + 16896;
    float* RQt = sm + 25600;
    __shared__ float redm[64][4], redl[64][4], mfin[64];

    int tid = threadIdx.x;
    int cid = blockIdx.x, wkv = blockIdx.y;
    int w = wkv >> 3, kv = wkv & 7;

    int seg, nl = 128, ownnew = 0;
    const float *ksrc, *vsrc;
    if (cid < 64) {
        seg = 0;
        size_t off = ((size_t)kv * 8192 + cid * 128) * 128;
        ksrc = ssk + off; vsrc = ssv + off;
    } else if (cid < 81) {
        seg = 1;
        int cc = cid - 64;
        if (cc < 16) {
            size_t off = ((size_t)kv * 2048 + cc * 128) * 128;
            ksrc = w0k + off; vsrc = w0v + off;
        } else {
            nl = 16; ownnew = (w == 0);
            size_t off = (size_t)kv * 16 * 128;
            ksrc = g_knew + off; vsrc = g_vnew + off;
        }
    } else {
        seg = 2;
        int cc = cid - 81;
        if (cc < 16) {
            size_t off = ((size_t)kv * 2048 + cc * 128) * 128;
            ksrc = w1k + off; vsrc = w1v + off;
        } else {
            nl = 16; ownnew = (w == 1);
            size_t off = (size_t)(8 + kv) * 16 * 128;
            ksrc = g_knew + off; vsrc = g_vnew + off;
        }
    }
    int pidx = wkv * 98 + cid;

    // ---- stage RQt[d][hq] (non-dup, 8192 floats) ----
    {
        const float4* s4 = (const float4*)(g_rqt + (size_t)((seg * 2 + w) * 8 + kv) * 8192);
#pragma unroll
        for (int r = 0; r < 8; r++) {
            int i = tid + r * 256;            // float4 index, [0,2048)
            int d = i >> 4, c = i & 15;       // row d, 4-float group c
            *(float4*)&RQt[d * 68 + 4 * c] = s4[i];
        }
    }
    // ---- stage K transposed: KT[d][key], stride 132 ----
#pragma unroll
    for (int r = 0; r < 16; r++) {
        int f = tid + r * 256;
        int key = f & 127, dq = f >> 7;      // dq: 4-dim group 0..31
        float4 v = (key < nl) ? ((const float4*)ksrc)[key * 32 + dq]
                              : make_float4(0.f, 0.f, 0.f, 0.f);
        KT[(4 * dq + 0) * 132 + key] = v.x;
        KT[(4 * dq + 1) * 132 + key] = v.y;
        KT[(4 * dq + 2) * 132 + key] = v.z;
        KT[(4 * dq + 3) * 132 + key] = v.w;
    }
    __syncthreads();

    int lane = tid & 31, wi = tid >> 5;
    int hh = wi & 3, q0 = (wi >> 2) * 8;     // head, q-half
    int hq0 = hh * 16 + q0;

    // ---- QK: acc[qp][j] = score pairs (q0+2qp, q0+2qp+1) x key (lane+32j) ----
    {
        ull acc[4][4];
#pragma unroll
        for (int a = 0; a < 4; a++)
#pragma unroll
            for (int b = 0; b < 4; b++) acc[a][b] = 0ULL;
#pragma unroll 4
        for (int d = 0; d < 128; d++) {
            ulonglong2 ra = *(const ulonglong2*)&RQt[d * 68 + hq0];
            ulonglong2 rb = *(const ulonglong2*)&RQt[d * 68 + hq0 + 4];
            float k0 = KT[d * 132 + lane];
            float k1 = KT[d * 132 + lane + 32];
            float k2 = KT[d * 132 + lane + 64];
            float k3 = KT[d * 132 + lane + 96];
            ull p0 = pk2(k0, k0), p1 = pk2(k1, k1);
            ull p2 = pk2(k2, k2), p3 = pk2(k3, k3);
            acc[0][0] = ffma2(ra.x, p0, acc[0][0]);
            acc[0][1] = ffma2(ra.x, p1, acc[0][1]);
            acc[0][2] = ffma2(ra.x, p2, acc[0][2]);
            acc[0][3] = ffma2(ra.x, p3, acc[0][3]);
            acc[1][0] = ffma2(ra.y, p0, acc[1][0]);
            acc[1][1] = ffma2(ra.y, p1, acc[1][1]);
            acc[1][2] = ffma2(ra.y, p2, acc[1][2]);
            acc[1][3] = ffma2(ra.y, p3, acc[1][3]);
            acc[2][0] = ffma2(rb.x, p0, acc[2][0]);
            acc[2][1] = ffma2(rb.x, p1, acc[2][1]);
            acc[2][2] = ffma2(rb.x, p2, acc[2][2]);
            acc[2][3] = ffma2(rb.x, p3, acc[2][3]);
            acc[3][0] = ffma2(rb.y, p0, acc[3][0]);
            acc[3][1] = ffma2(rb.y, p1, acc[3][1]);
            acc[3][2] = ffma2(rb.y, p2, acc[3][2]);
            acc[3][3] = ffma2(rb.y, p3, acc[3][3]);
        }
        // mask + store transposed scores SCt[key][hq] (pair = q,q+1)
#pragma unroll
        for (int qp = 0; qp < 4; qp++) {
            int qa = q0 + 2 * qp;
#pragma unroll
            for (int j = 0; j < 4; j++) {
                int key = lane + 32 * j;
                float2 s = unpk(acc[qp][j]);
                bool vis = key < nl;
                float e0 = (vis && (!ownnew || key <= qa))     ? s.x * SCALE : -1e30f;
                float e1 = (vis && (!ownnew || key <= qa + 1)) ? s.y * SCALE : -1e30f;
                *(float2*)&SCt[key * 68 + hh * 16 + qa] = make_float2(e0, e1);
            }
        }
    }
    __syncthreads();

    // ---- stage V (reuse KT region): V[l][dim], stride 132 ----
#pragma unroll
    for (int r = 0; r < 16; r++) {
        int f = tid + r * 256;
        int l = f >> 5, dq = f & 31;
        float4 v = (l < nl) ? ((const float4*)vsrc)[l * 32 + dq]
                            : make_float4(0.f, 0.f, 0.f, 0.f);
        *(float4*)&KT[l * 132 + 4 * dq] = v;
    }

    // ---- per-chunk softmax on SCt columns ----
    {
        int hq = tid & 63, part = tid >> 6;   // 4 parts x 32 keys
        float m = -1e30f;
#pragma unroll
        for (int i = 0; i < 32; i++)
            m = fmaxf(m, SCt[(part * 32 + i) * 68 + hq]);
        redm[hq][part] = m;
        __syncthreads();
        if (tid < 64)
            mfin[tid] = fmaxf(fmaxf(redm[tid][0], redm[tid][1]),
                              fmaxf(redm[tid][2], redm[tid][3]));
        __syncthreads();
        float mm = mfin[hq];
        float s = 0.f;
#pragma unroll
        for (int i = 0; i < 32; i++) {
            int idx = (part * 32 + i) * 68 + hq;
            float p = __expf(SCt[idx] - mm);
            SCt[idx] = p;
            s += p;
        }
        redl[hq][part] = s;
        __syncthreads();
        if (tid < 64) {
            float L = redl[tid][0] + redl[tid][1] + redl[tid][2] + redl[tid][3];
            g_pm[(size_t)pidx * 64 + tid] = mfin[tid];
            g_pl[(size_t)pidx * 64 + tid] = L;
        }
        __syncthreads();   // probs + V both ready
    }

    // ---- PV: acc[qp][j] = out pairs (q,q+1) x dim (lane+32j) ----
    {
        ull acc[4][4];
#pragma unroll
        for (int a = 0; a < 4; a++)
#pragma unroll
            for (int b = 0; b < 4; b++) acc[a][b] = 0ULL;
#pragma unroll 4
        for (int l = 0; l < 128; l++) {
            ulonglong2 ra = *(const ulonglong2*)&SCt[l * 68 + hq0];
            ulonglong2 rb = *(const ulonglong2*)&SCt[l * 68 + hq0 + 4];
            float v0 = KT[l * 132 + lane];
            float v1 = KT[l * 132 + lane + 32];
            float v2 = KT[l * 132 + lane + 64];
            float v3 = KT[l * 132 + lane + 96];
            ull p0 = pk2(v0, v0), p1 = pk2(v1, v1);
            ull p2 = pk2(v2, v2), p3 = pk2(v3, v3);
            acc[0][0] = ffma2(ra.x, p0, acc[0][0]);
            acc[0][1] = ffma2(ra.x, p1, acc[0][1]);
            acc[0][2] = ffma2(ra.x, p2, acc[0][2]);
            acc[0][3] = ffma2(ra.x, p3, acc[0][3]);
            acc[1][0] = ffma2(ra.y, p0, acc[1][0]);
            acc[1][1] = ffma2(ra.y, p1, acc[1][1]);
            acc[1][2] = ffma2(ra.y, p2, acc[1][2]);
            acc[1][3] = ffma2(ra.y, p3, acc[1][3]);
            acc[2][0] = ffma2(rb.x, p0, acc[2][0]);
            acc[2][1] = ffma2(rb.x, p1, acc[2][1]);
            acc[2][2] = ffma2(rb.x, p2, acc[2][2]);
            acc[2][3] = ffma2(rb.x, p3, acc[2][3]);
            acc[3][0] = ffma2(rb.y, p0, acc[3][0]);
            acc[3][1] = ffma2(rb.y, p1, acc[3][1]);
            acc[3][2] = ffma2(rb.y, p2, acc[3][2]);
            acc[3][3] = ffma2(rb.y, p3, acc[3][3]);
        }
#pragma unroll
        for (int qp = 0; qp < 4; qp++) {
            int hqa = hq0 + 2 * qp;
#pragma unroll
            for (int j = 0; j < 4; j++) {
                int dim = lane + 32 * j;
                float2 a = unpk(acc[qp][j]);
                g_pacc[((size_t)pidx * 64 + hqa) * 128 + dim]     = a.x;
                g_pacc[((size_t)pidx * 64 + hqa + 1) * 128 + dim] = a.y;
            }
        }
    }
}

// split-K combine: grid 1024 = (w,h,q), 128 threads
__global__ __launch_bounds__(128) void combine_kernel() {
    __shared__ float swgt[98];
    __shared__ float redA[4], redB[4];
    int b = blockIdx.x;
    int q = b & 15, h = (b >> 4) & 31, w = b >> 9;
    int kv = h >> 2;
    int hq = (h & 3) * 16 + q;
    size_t base = (size_t)(w * 8 + kv) * 98;
    int tid = threadIdx.x;

    float pm = (tid < 98) ? g_pm[(base + tid) * 64 + hq] : -3e38f;
    float pl = (tid < 98) ? g_pl[(base + tid) * 64 + hq] : 0.f;
    float m = pm;
#pragma unroll
    for (int o = 16; o; o >>= 1) m = fmaxf(m, __shfl_xor_sync(0xffffffffu, m, o));
    if ((tid & 31) == 0) redA[tid >> 5] = m;
    __syncthreads();
    float M = fmaxf(fmaxf(redA[0], redA[1]), fmaxf(redA[2], redA[3]));
    float wgt = __expf(pm - M);
    if (tid < 98) swgt[tid] = wgt;
    float l = (tid < 98) ? pl * wgt : 0.f;
#pragma unroll
    for (int o = 16; o; o >>= 1) l += __shfl_xor_sync(0xffffffffu, l, o);
    if ((tid & 31) == 0) redB[tid >> 5] = l;
    __syncthreads();
    float L = redB[0] + redB[1] + redB[2] + redB[3];

    float A = 0.f;
#pragma unroll 7
    for (int c = 0; c < 98; c++)
        A += g_pacc[((base + c) * 64 + hq) * 128 + tid] * swgt[c];
    int t = w * 16 + q;
    g_attn[(size_t)t * 4096 + h * 128 + tid] = A / L;
}

// ----------------------------- launch ---------------------------------------
extern "C" void kernel_launch(void* const* d_in, const int* in_sizes, int n_in,
                              void* d_out, int out_size) {
    const float* hs   = (const float*)d_in[0];
    const float* Wq   = (const float*)d_in[1];
    const float* bq   = (const float*)d_in[2];
    const float* Wk   = (const float*)d_in[3];
    const float* bk   = (const float*)d_in[4];
    const float* Wv   = (const float*)d_in[5];
    const float* bv   = (const float*)d_in[6];
    const float* Wo   = (const float*)d_in[7];
    const float* ssk  = (const float*)d_in[8];
    const float* ssv  = (const float*)d_in[9];
    const float* w0k  = (const float*)d_in[10];
    const float* w0v  = (const float*)d_in[11];
    const float* w1k  = (const float*)d_in[12];
    const float* w1v  = (const float*)d_in[13];
    const float* cosn = (const float*)d_in[14];
    const float* sinn = (const float*)d_in[15];
    float* out = (float*)d_out;

    cudaFuncSetAttribute(attn_kernel,
                         cudaFuncAttributeMaxDynamicSharedMemorySize, 137216);

    qkv_gemm_kernel<<<dim3(48, 16), 256>>>(hs, Wq, Wk, Wv);
    reduce_qkv_kernel<<<768, 256>>>(bq, bk, bv);
    rope_all_kernel<<<3328, 128>>>(cosn, sinn);

    attn_kernel<<<dim3(98, 16), 256, 137216>>>(ssk, ssv, w0k, w0v, w1k, w1v);
    combine_kernel<<<1024, 128>>>();

    o_gemm_kernel<<<dim3(32, 16), 256>>>(Wo);
    reduce_out_kernel<<<512, 256>>>(out);
}